// round 1
// baseline (speedup 1.0000x reference)
#include <cuda_runtime.h>
#include <math.h>

#define Bb 2
#define Nn 1024
#define Cc 768
#define Hh 12
#define Dd 64
#define ATT_SCALE 0.125f   // D^-0.5

// ---------------- scratch (static device memory; no allocations) ----------------
__device__ float g_qkv[Bb * Nn * 3 * Cc];      // [b, n, s, h, d] contiguous = [2048, 2304]
__device__ float g_z  [Bb * Nn * Hh];          // gate logits
__device__ float g_c  [Bb * Hh * (Nn + 1)];    // prefix sums of log a
__device__ float g_ao [Bb * Nn * Cc];          // attention output [b, n, h, d]

#define OUTER4(ACC, A4, B4) do { \
  ACC[0][0] += A4.x*B4.x; ACC[0][1] += A4.x*B4.y; ACC[0][2] += A4.x*B4.z; ACC[0][3] += A4.x*B4.w; \
  ACC[1][0] += A4.y*B4.x; ACC[1][1] += A4.y*B4.y; ACC[1][2] += A4.y*B4.z; ACC[1][3] += A4.y*B4.w; \
  ACC[2][0] += A4.z*B4.x; ACC[2][1] += A4.z*B4.y; ACC[2][2] += A4.z*B4.z; ACC[2][3] += A4.z*B4.w; \
  ACC[3][0] += A4.w*B4.x; ACC[3][1] += A4.w*B4.y; ACC[3][2] += A4.w*B4.z; ACC[3][3] += A4.w*B4.w; \
} while (0)

// ---------------- GEMM: C[M,N] = A[M,K] @ B[N,K]^T (+ optional bias[N]) ----------------
// 64x64 tile, BK=16, 256 threads, 4x4 microtile per thread.
__global__ __launch_bounds__(256) void gemm_tn(
    const float* __restrict__ A, const float* __restrict__ B,
    const float* __restrict__ bias, float* __restrict__ Cout,
    int M, int N, int K)
{
  __shared__ float AsT[16][68];   // [k][m], 68-float rows: 272B (16B aligned, conflict-free)
  __shared__ float BsT[16][68];   // [k][n]
  const int m0 = blockIdx.y * 64;
  const int n0 = blockIdx.x * 64;
  const int t  = threadIdx.x;
  const int tx = t & 15;          // n group
  const int ty = t >> 4;          // m group
  const int lrow = t >> 2;        // 0..63
  const int lkq  = (t & 3) * 4;   // 0,4,8,12

  float acc[4][4] = {};
  const float* Aptr = A + (size_t)(m0 + lrow) * K + lkq;
  const float* Bptr = B + (size_t)(n0 + lrow) * K + lkq;

  for (int k0 = 0; k0 < K; k0 += 16) {
    float4 a4 = *(const float4*)(Aptr + k0);
    float4 b4 = *(const float4*)(Bptr + k0);
    __syncthreads();
    AsT[lkq+0][lrow] = a4.x; AsT[lkq+1][lrow] = a4.y; AsT[lkq+2][lrow] = a4.z; AsT[lkq+3][lrow] = a4.w;
    BsT[lkq+0][lrow] = b4.x; BsT[lkq+1][lrow] = b4.y; BsT[lkq+2][lrow] = b4.z; BsT[lkq+3][lrow] = b4.w;
    __syncthreads();
    #pragma unroll
    for (int k = 0; k < 16; k++) {
      float4 av = *(const float4*)&AsT[k][ty * 4];
      float4 bv = *(const float4*)&BsT[k][tx * 4];
      OUTER4(acc, av, bv);
    }
  }

  float4 bb = make_float4(0.f, 0.f, 0.f, 0.f);
  if (bias) bb = *(const float4*)&bias[n0 + tx * 4];
  #pragma unroll
  for (int ii = 0; ii < 4; ii++) {
    float4 o;
    o.x = acc[ii][0] + bb.x; o.y = acc[ii][1] + bb.y;
    o.z = acc[ii][2] + bb.z; o.w = acc[ii][3] + bb.w;
    *(float4*)&Cout[(size_t)(m0 + ty * 4 + ii) * N + n0 + tx * 4] = o;
  }
}

// ---------------- gate logits: z[b,n,h] = x[b,n,:] . Wa[h,:] + ba[h] ----------------
__global__ __launch_bounds__(256) void gate_logits(
    const float* __restrict__ x, const float* __restrict__ Wa, const float* __restrict__ ba)
{
  __shared__ float sW[Hh * Cc];   // 36 KB
  const int t = threadIdx.x;
  for (int i = t; i < Hh * Cc; i += 256) sW[i] = Wa[i];
  __syncthreads();

  const int warp = t >> 5, lane = t & 31;
  const int row = blockIdx.x * 8 + warp;   // 0..2047
  const float* xr = x + (size_t)row * Cc;

  float acc[Hh] = {};
  for (int c0 = 0; c0 < Cc; c0 += 32) {
    float xv = xr[c0 + lane];
    #pragma unroll
    for (int h = 0; h < Hh; h++) acc[h] += xv * sW[h * Cc + c0 + lane];
  }
  #pragma unroll
  for (int h = 0; h < Hh; h++) {
    float v = acc[h];
    #pragma unroll
    for (int o = 16; o; o >>= 1) v += __shfl_xor_sync(0xffffffffu, v, o);
    if (lane == 0) g_z[(size_t)row * Hh + h] = v + ba[h];
  }
}

// ---------------- per-(b,h) scan: c[m] = sum_{t<m} log a[t], a[0]=1, a[n]=sigmoid(-z[n]) ----
__global__ __launch_bounds__(1024) void gate_scan()
{
  __shared__ float sh[1024];
  const int bh = blockIdx.x;
  const int b = bh / Hh, h = bh % Hh;
  const int t = threadIdx.x;

  float la = 0.f;
  if (t > 0) {
    float z = g_z[((size_t)b * Nn + t) * Hh + h];
    // log a = log sigmoid(-z) = -softplus(z)
    float sp = (z > 15.f) ? z : log1pf(__expf(z));
    la = -sp;
  }
  sh[t] = la;
  __syncthreads();
  #pragma unroll
  for (int off = 1; off < 1024; off <<= 1) {
    float v = (t >= off) ? sh[t - off] : 0.f;
    __syncthreads();
    sh[t] += v;
    __syncthreads();
  }
  float* cp = g_c + (size_t)bh * (Nn + 1);
  if (t == 0) cp[0] = 0.f;
  cp[t + 1] = sh[t];
}

// ---------------- q/k: silu(z)+0.5, L2-normalize over D (in place in g_qkv) ----------------
__global__ __launch_bounds__(256) void qk_norm()
{
  const int bn = blockIdx.x;                 // 0..2047
  const int warp = threadIdx.x >> 5, lane = threadIdx.x & 31;
  for (int task = warp; task < 2 * Hh; task += 8) {
    const int s = task & 1, h = task >> 1;
    float* p = g_qkv + (size_t)bn * 3 * Cc + s * Cc + h * Dd;
    float v0 = p[lane], v1 = p[lane + 32];
    float r0 = v0 / (1.f + __expf(-v0)) + 0.5f;
    float r1 = v1 / (1.f + __expf(-v1)) + 0.5f;
    float ss = r0 * r0 + r1 * r1;
    #pragma unroll
    for (int o = 16; o; o >>= 1) ss += __shfl_xor_sync(0xffffffffu, ss, o);
    float inv = rsqrtf(ss);
    p[lane] = r0 * inv;
    p[lane + 32] = r1 * inv;
  }
}

// ---------------- attention: 64 i-rows per block, stream over 16 j-tiles of 64 ----------------
// attn[i,j] = (q_i.k_j)*SCALE*M[i,j];  out_i = (sum_j attn[i,j] v_j) / (sum_j attn[i,j] + 1e-6)
// M[i,j] = exp(c[i]-c[j]) if j<i; 1 if j==i; exp(c[j+1]-c[i+1]) if j>i.  (args always <= 0)
__global__ __launch_bounds__(256) void attn_kernel(
    const float* __restrict__ qkv, const float* __restrict__ cbuf, float* __restrict__ ao)
{
  extern __shared__ float sm[];
  float* QsT = sm;                 // [d][i] 64x68
  float* KsT = QsT + 64 * 68;      // [d][j] 64x68
  float* Vs  = KsT + 64 * 68;      // [j][d] 64x68
  float* SsT = Vs  + 64 * 68;      // [j][i] 64x68
  float* ci  = SsT + 64 * 68;      // 64
  float* ci1 = ci  + 64;           // 64
  float* cj  = ci1 + 64;           // 64
  float* cj1 = cj  + 64;           // 64
  float* rs  = cj1 + 64;           // [i][16] rowsum partials

  const int bh = blockIdx.x;
  const int b = bh / Hh, h = bh % Hh;
  const int i0 = blockIdx.y * 64;
  const int t = threadIdx.x;
  const int tx = t & 15;           // j (phase A) / d (phase B) group
  const int ty = t >> 4;           // i group

  const float* cb = cbuf + (size_t)bh * (Nn + 1);
  const float* qbase = qkv + (size_t)b * Nn * 3 * Cc + h * Dd;
  const float* kbase = qbase + Cc;
  const float* vbase = qbase + 2 * Cc;

  // load Q tile transposed
  #pragma unroll
  for (int r = 0; r < 4; r++) {
    int idx = t + r * 256;
    int row = idx >> 4, dq = (idx & 15) << 2;
    float4 q4 = *(const float4*)(qbase + (size_t)(i0 + row) * 3 * Cc + dq);
    QsT[(dq + 0) * 68 + row] = q4.x; QsT[(dq + 1) * 68 + row] = q4.y;
    QsT[(dq + 2) * 68 + row] = q4.z; QsT[(dq + 3) * 68 + row] = q4.w;
  }
  if (t < 64) { ci[t] = cb[i0 + t]; ci1[t] = cb[i0 + t + 1]; }

  float acc[4][4] = {};
  float rsum[4] = {};

  for (int jt = 0; jt < 16; jt++) {
    const int j0 = jt * 64;
    __syncthreads();   // previous phase B finished with Vs/SsT
    #pragma unroll
    for (int r = 0; r < 4; r++) {
      int idx = t + r * 256;
      int row = idx >> 4, dq = (idx & 15) << 2;
      float4 k4 = *(const float4*)(kbase + (size_t)(j0 + row) * 3 * Cc + dq);
      KsT[(dq + 0) * 68 + row] = k4.x; KsT[(dq + 1) * 68 + row] = k4.y;
      KsT[(dq + 2) * 68 + row] = k4.z; KsT[(dq + 3) * 68 + row] = k4.w;
      float4 v4 = *(const float4*)(vbase + (size_t)(j0 + row) * 3 * Cc + dq);
      *(float4*)&Vs[row * 68 + dq] = v4;
    }
    if (t < 64) { cj[t] = cb[j0 + t]; cj1[t] = cb[j0 + t + 1]; }
    __syncthreads();

    // phase A: scores s[4i][4j]
    float s[4][4] = {};
    #pragma unroll 16
    for (int d = 0; d < 64; d++) {
      float4 q4 = *(const float4*)&QsT[d * 68 + ty * 4];
      float4 k4 = *(const float4*)&KsT[d * 68 + tx * 4];
      OUTER4(s, q4, k4);
    }
    // apply mask + scale, accumulate row sums, stage to shared (transposed)
    #pragma unroll
    for (int jj = 0; jj < 4; jj++) {
      const int jl = tx * 4 + jj;
      const int jg = j0 + jl;
      const float cjv = cj[jl], cj1v = cj1[jl];
      #pragma unroll
      for (int ii = 0; ii < 4; ii++) {
        const int il = ty * 4 + ii;
        const int ig = i0 + il;
        float arg = (jg < ig) ? (ci[il] - cjv) : ((jg > ig) ? (cj1v - ci1[il]) : 0.f);
        float w = s[ii][jj] * ATT_SCALE * __expf(arg);
        rsum[ii] += w;
        SsT[jl * 68 + il] = w;
      }
    }
    __syncthreads();

    // phase B: acc[4i][4d] += S^T . V
    #pragma unroll 8
    for (int j = 0; j < 64; j++) {
      float4 s4 = *(const float4*)&SsT[j * 68 + ty * 4];
      float4 v4 = *(const float4*)&Vs[j * 68 + tx * 4];
      OUTER4(acc, s4, v4);
    }
  }

  // reduce row sums across the 16 tx groups
  #pragma unroll
  for (int ii = 0; ii < 4; ii++) rs[(ty * 4 + ii) * 16 + tx] = rsum[ii];
  __syncthreads();
  #pragma unroll
  for (int ii = 0; ii < 4; ii++) {
    const int il = ty * 4 + ii;
    float tot = 0.f;
    #pragma unroll
    for (int g = 0; g < 16; g++) tot += rs[il * 16 + g];
    float inv = 1.f / (tot + 1e-6f);
    float4 o;
    o.x = acc[ii][0] * inv; o.y = acc[ii][1] * inv;
    o.z = acc[ii][2] * inv; o.w = acc[ii][3] * inv;
    *(float4*)&ao[((size_t)(b * Nn + i0 + il)) * Cc + h * Dd + tx * 4] = o;
  }
}

// ---------------- launch ----------------
extern "C" void kernel_launch(void* const* d_in, const int* in_sizes, int n_in,
                              void* d_out, int out_size)
{
  const float* x     = (const float*)d_in[0];
  const float* Wqkv  = (const float*)d_in[1];
  const float* Wa    = (const float*)d_in[2];
  const float* ba    = (const float*)d_in[3];
  const float* Wproj = (const float*)d_in[4];
  const float* bproj = (const float*)d_in[5];
  float* out = (float*)d_out;

  float *qkv, *cbuf, *aobuf;
  cudaGetSymbolAddress((void**)&qkv,   g_qkv);
  cudaGetSymbolAddress((void**)&cbuf,  g_c);
  cudaGetSymbolAddress((void**)&aobuf, g_ao);

  const int SMEM_ATTN = (4 * 64 * 68 + 4 * 64 + 64 * 16) * (int)sizeof(float); // 74752 B
  cudaFuncSetAttribute(attn_kernel, cudaFuncAttributeMaxDynamicSharedMemorySize, SMEM_ATTN);

  // 1) qkv = x @ Wqkv^T   [2048 x 2304]
  gemm_tn<<<dim3(3 * Cc / 64, Bb * Nn / 64), 256>>>(x, Wqkv, nullptr, qkv, Bb * Nn, 3 * Cc, Cc);
  // 2) gate logits
  gate_logits<<<Bb * Nn / 8, 256>>>(x, Wa, ba);
  // 3) prefix-sum of log gates per (b,h)
  gate_scan<<<Bb * Hh, 1024>>>();
  // 4) q/k silu+0.5 + L2 norm, in place
  qk_norm<<<Bb * Nn, 256>>>();
  // 5) attention
  attn_kernel<<<dim3(Bb * Hh, Nn / 64), 256, SMEM_ATTN>>>(qkv, cbuf, aobuf);
  // 6) out = ao @ Wproj^T + bproj
  gemm_tn<<<dim3(Cc / 64, Bb * Nn / 64), 256>>>(aobuf, Wproj, bproj, out, Bb * Nn, Cc, Cc);
}

// round 3
// speedup vs baseline: 1.5241x; 1.5241x over previous
#include <cuda_runtime.h>
#include <cuda_bf16.h>
#include <math.h>
#include <cstdint>

#define Bb 2
#define Nn 1024
#define Cc 768
#define Hh 12
#define Dd 64
#define ATT_SCALE 0.125f   // D^-0.5

// ---------------- scratch (static device memory; no allocations) ----------------
__device__ float g_qkv[Bb * Nn * 3 * Cc];      // [b, n, s, h, d] contiguous = [2048, 2304]
__device__ float g_z  [Bb * Nn * Hh];          // gate logits
__device__ float g_c  [Bb * Hh * (Nn + 1)];    // prefix sums of log a
__device__ float g_ao [Bb * Nn * Cc];          // attention output [b, n, h, d]

__device__ __forceinline__ uint32_t smem_u32(const void* p) {
  uint32_t a;
  asm("{ .reg .u64 t; cvta.to.shared.u64 t, %1; cvt.u32.u64 %0, t; }" : "=r"(a) : "l"(p));
  return a;
}

#define LDSM4(R0, R1, R2, R3, addr) \
  asm volatile("ldmatrix.sync.aligned.m8n8.x4.shared.b16 {%0,%1,%2,%3}, [%4];" \
               : "=r"(R0), "=r"(R1), "=r"(R2), "=r"(R3) : "r"(addr))

#define MMA16816(C, A0, A1, A2, A3, B0, B1) \
  asm volatile("mma.sync.aligned.m16n8k16.row.col.f32.bf16.bf16.f32 " \
               "{%0,%1,%2,%3}, {%4,%5,%6,%7}, {%8,%9}, {%0,%1,%2,%3};" \
               : "+f"((C)[0]), "+f"((C)[1]), "+f"((C)[2]), "+f"((C)[3]) \
               : "r"(A0), "r"(A1), "r"(A2), "r"(A3), "r"(B0), "r"(B1))

// split fp32x8 -> bf16 hi/lo x8 (2-term split; dropped lo*lo ~ 2^-16 relative)
__device__ __forceinline__ void cvt8(const float4 a, const float4 b, uint4& hi, uint4& lo) {
  __nv_bfloat162 h; float2 f; __nv_bfloat162 l;
  h = __floats2bfloat162_rn(a.x, a.y); hi.x = *(uint32_t*)&h; f = __bfloat1622float2(h);
  l = __floats2bfloat162_rn(a.x - f.x, a.y - f.y); lo.x = *(uint32_t*)&l;
  h = __floats2bfloat162_rn(a.z, a.w); hi.y = *(uint32_t*)&h; f = __bfloat1622float2(h);
  l = __floats2bfloat162_rn(a.z - f.x, a.w - f.y); lo.y = *(uint32_t*)&l;
  h = __floats2bfloat162_rn(b.x, b.y); hi.z = *(uint32_t*)&h; f = __bfloat1622float2(h);
  l = __floats2bfloat162_rn(b.x - f.x, b.y - f.y); lo.z = *(uint32_t*)&l;
  h = __floats2bfloat162_rn(b.z, b.w); hi.w = *(uint32_t*)&h; f = __bfloat1622float2(h);
  l = __floats2bfloat162_rn(b.z - f.x, b.w - f.y); lo.w = *(uint32_t*)&l;
}

// ============ tensor-core GEMM (bf16 3-pass split): C[M,N] = A[M,K] @ B[N,K]^T (+bias) ======
// CTA 128x128, 8 warps in 2(m) x 4(n); warp tile 64x32 = 4x4 m16n8k16 frags.
// SMEM stage: A[128 rows x (16 hi bf16 | 16 lo bf16 | pad)] pitch 80B, then B same. Double buffered.
#define GPITCH 80
#define GMAT   (128 * GPITCH)       // 10240
#define GSTAGE (2 * GMAT)           // 20480
#define GSMEM  (2 * GSTAGE)         // 40960

__global__ __launch_bounds__(256, 1) void gemm_mma(
    const float* __restrict__ A, const float* __restrict__ B,
    const float* __restrict__ bias, float* __restrict__ Cout,
    int M, int N, int K)
{
  extern __shared__ char smc[];
  const uint32_t sb = smem_u32(smc);
  const int tid = threadIdx.x, wid = tid >> 5, lane = tid & 31;
  const int m0 = blockIdx.y * 128, n0 = blockIdx.x * 128;
  const int wm = (wid & 1) * 64, wn = (wid >> 1) * 32;

  // global load assignment: thread t -> row t>>1 (0..127), col (t&1)*8
  const int lrow = tid >> 1;
  const int lcol = (tid & 1) * 8;
  const float* Ag = A + (size_t)(m0 + lrow) * K + lcol;
  const float* Bg = B + (size_t)(n0 + lrow) * K + lcol;
  const uint32_t stA = sb + lrow * GPITCH + (lcol ? 16 : 0);   // hi bytes; lo at +32
  const uint32_t stB = stA + GMAT;

  // ldmatrix addresses (within a stage)
  // A (m16k16 x4): row = wm + mt*16 + (lane&15), colbyte = (lane>>4)*16
  const uint32_t aoff = (uint32_t)((wm + (lane & 15)) * GPITCH + ((lane >> 4) * 16));
  // B (two n8k16 per x4): row = wn + g*16 + ((lane>>4)<<3) + (lane&7), colbyte = ((lane>>3)&1)*16
  const uint32_t boff = (uint32_t)((wn + ((lane >> 4) << 3) + (lane & 7)) * GPITCH
                                   + (((lane >> 3) & 1) * 16)) + GMAT;

  float c[4][4][4] = {};
  const int NK = K / 16;

  float4 pa0, pa1, pb0, pb1;
  pa0 = *(const float4*)(Ag);     pa1 = *(const float4*)(Ag + 4);
  pb0 = *(const float4*)(Bg);     pb1 = *(const float4*)(Bg + 4);
  {
    uint4 hi, lo;
    cvt8(pa0, pa1, hi, lo);
    *(uint4*)(smc + (stA - sb))      = hi;
    *(uint4*)(smc + (stA - sb) + 32) = lo;
    cvt8(pb0, pb1, hi, lo);
    *(uint4*)(smc + (stB - sb))      = hi;
    *(uint4*)(smc + (stB - sb) + 32) = lo;
  }
  __syncthreads();

  for (int kc = 0; kc < NK; kc++) {
    const int s = kc & 1;
    if (kc + 1 < NK) {
      pa0 = *(const float4*)(Ag + (kc + 1) * 16);
      pa1 = *(const float4*)(Ag + (kc + 1) * 16 + 4);
      pb0 = *(const float4*)(Bg + (kc + 1) * 16);
      pb1 = *(const float4*)(Bg + (kc + 1) * 16 + 4);
    }

    const uint32_t stg = sb + s * GSTAGE;
    uint32_t ahi[4][4], alo[4][4], bhi[2][4], blo[2][4];
    #pragma unroll
    for (int mt = 0; mt < 4; mt++) {
      uint32_t ad = stg + aoff + mt * (16 * GPITCH);
      LDSM4(ahi[mt][0], ahi[mt][1], ahi[mt][2], ahi[mt][3], ad);
      LDSM4(alo[mt][0], alo[mt][1], alo[mt][2], alo[mt][3], ad + 32);
    }
    #pragma unroll
    for (int g = 0; g < 2; g++) {
      uint32_t bd = stg + boff + g * (16 * GPITCH);
      LDSM4(bhi[g][0], bhi[g][1], bhi[g][2], bhi[g][3], bd);
      LDSM4(blo[g][0], blo[g][1], blo[g][2], blo[g][3], bd + 32);
    }

    #pragma unroll
    for (int mt = 0; mt < 4; mt++) {
      #pragma unroll
      for (int nt = 0; nt < 4; nt++) {
        const int g = nt >> 1, q = (nt & 1) * 2;
        MMA16816(c[mt][nt], ahi[mt][0], ahi[mt][1], ahi[mt][2], ahi[mt][3], bhi[g][q], bhi[g][q + 1]);
        MMA16816(c[mt][nt], ahi[mt][0], ahi[mt][1], ahi[mt][2], ahi[mt][3], blo[g][q], blo[g][q + 1]);
        MMA16816(c[mt][nt], alo[mt][0], alo[mt][1], alo[mt][2], alo[mt][3], bhi[g][q], bhi[g][q + 1]);
      }
    }

    if (kc + 1 < NK) {
      const uint32_t dst = (stA - sb) + ((kc + 1) & 1) * GSTAGE;
      uint4 hi, lo;
      cvt8(pa0, pa1, hi, lo);
      *(uint4*)(smc + dst)      = hi;
      *(uint4*)(smc + dst + 32) = lo;
      cvt8(pb0, pb1, hi, lo);
      *(uint4*)(smc + dst + GMAT)      = hi;
      *(uint4*)(smc + dst + GMAT + 32) = lo;
    }
    __syncthreads();
  }

  // epilogue: c frag thread map: c0,c1 -> (row lane>>2, col (lane&3)*2); c2,c3 -> row+8
  #pragma unroll
  for (int mt = 0; mt < 4; mt++) {
    const int row = m0 + wm + mt * 16 + (lane >> 2);
    #pragma unroll
    for (int nt = 0; nt < 4; nt++) {
      const int col = n0 + wn + nt * 8 + (lane & 3) * 2;
      float bx = 0.f, by = 0.f;
      if (bias) { bx = __ldg(&bias[col]); by = __ldg(&bias[col + 1]); }
      *(float2*)&Cout[(size_t)row * N + col] =
          make_float2(c[mt][nt][0] + bx, c[mt][nt][1] + by);
      *(float2*)&Cout[(size_t)(row + 8) * N + col] =
          make_float2(c[mt][nt][2] + bx, c[mt][nt][3] + by);
    }
  }
}

// ---------------- gate logits: z[b,n,h] = x[b,n,:] . Wa[h,:] + ba[h] ----------------
__global__ __launch_bounds__(256) void gate_logits(
    const float* __restrict__ x, const float* __restrict__ Wa, const float* __restrict__ ba)
{
  __shared__ float sW[Hh * Cc];   // 36 KB
  const int t = threadIdx.x;
  for (int i = t; i < Hh * Cc; i += 256) sW[i] = Wa[i];
  __syncthreads();

  const int warp = t >> 5, lane = t & 31;
  const int row = blockIdx.x * 8 + warp;   // 0..2047
  const float* xr = x + (size_t)row * Cc;

  float acc[Hh] = {};
  for (int c0 = 0; c0 < Cc; c0 += 32) {
    float xv = xr[c0 + lane];
    #pragma unroll
    for (int h = 0; h < Hh; h++) acc[h] += xv * sW[h * Cc + c0 + lane];
  }
  #pragma unroll
  for (int h = 0; h < Hh; h++) {
    float v = acc[h];
    #pragma unroll
    for (int o = 16; o; o >>= 1) v += __shfl_xor_sync(0xffffffffu, v, o);
    if (lane == 0) g_z[(size_t)row * Hh + h] = v + ba[h];
  }
}

// ---------------- per-(b,h) scan: c[m] = sum_{t<m} log a[t], a[0]=1, a[n]=sigmoid(-z[n]) ----
__global__ __launch_bounds__(1024) void gate_scan()
{
  __shared__ float sh[1024];
  const int bh = blockIdx.x;
  const int b = bh / Hh, h = bh % Hh;
  const int t = threadIdx.x;

  float la = 0.f;
  if (t > 0) {
    float z = g_z[((size_t)b * Nn + t) * Hh + h];
    float sp = (z > 15.f) ? z : log1pf(__expf(z));   // softplus
    la = -sp;
  }
  sh[t] = la;
  __syncthreads();
  #pragma unroll
  for (int off = 1; off < 1024; off <<= 1) {
    float v = (t >= off) ? sh[t - off] : 0.f;
    __syncthreads();
    sh[t] += v;
    __syncthreads();
  }
  float* cp = g_c + (size_t)bh * (Nn + 1);
  if (t == 0) cp[0] = 0.f;
  cp[t + 1] = sh[t];
}

// ---------------- q/k: silu(z)+0.5, L2-normalize over D (in place in g_qkv) ----------------
__global__ __launch_bounds__(256) void qk_norm()
{
  const int bn = blockIdx.x;                 // 0..2047
  const int warp = threadIdx.x >> 5, lane = threadIdx.x & 31;
  for (int task = warp; task < 2 * Hh; task += 8) {
    const int s = task & 1, h = task >> 1;
    float* p = g_qkv + (size_t)bn * 3 * Cc + s * Cc + h * Dd;
    float v0 = p[lane], v1 = p[lane + 32];
    float r0 = v0 / (1.f + __expf(-v0)) + 0.5f;
    float r1 = v1 / (1.f + __expf(-v1)) + 0.5f;
    float ss = r0 * r0 + r1 * r1;
    #pragma unroll
    for (int o = 16; o; o >>= 1) ss += __shfl_xor_sync(0xffffffffu, ss, o);
    float inv = rsqrtf(ss);
    p[lane] = r0 * inv;
    p[lane + 32] = r1 * inv;
  }
}

#define OUTER4(ACC, A4, B4) do { \
  ACC[0][0] += A4.x*B4.x; ACC[0][1] += A4.x*B4.y; ACC[0][2] += A4.x*B4.z; ACC[0][3] += A4.x*B4.w; \
  ACC[1][0] += A4.y*B4.x; ACC[1][1] += A4.y*B4.y; ACC[1][2] += A4.y*B4.z; ACC[1][3] += A4.y*B4.w; \
  ACC[2][0] += A4.z*B4.x; ACC[2][1] += A4.z*B4.y; ACC[2][2] += A4.z*B4.z; ACC[2][3] += A4.z*B4.w; \
  ACC[3][0] += A4.w*B4.x; ACC[3][1] += A4.w*B4.y; ACC[3][2] += A4.w*B4.z; ACC[3][3] += A4.w*B4.w; \
} while (0)

// ---------------- attention: 64 i-rows per block, stream over 16 j-tiles of 64 ----------------
__global__ __launch_bounds__(256) void attn_kernel(
    const float* __restrict__ qkv, const float* __restrict__ cbuf, float* __restrict__ ao)
{
  extern __shared__ float sm[];
  float* QsT = sm;                 // [d][i] 64x68
  float* KsT = QsT + 64 * 68;      // [d][j] 64x68
  float* Vs  = KsT + 64 * 68;      // [j][d] 64x68
  float* SsT = Vs  + 64 * 68;      // [j][i] 64x68
  float* ci  = SsT + 64 * 68;      // 64
  float* ci1 = ci  + 64;           // 64
  float* cj  = ci1 + 64;           // 64
  float* cj1 = cj  + 64;           // 64
  float* rs  = cj1 + 64;           // [i][16] rowsum partials

  const int bh = blockIdx.x;
  const int b = bh / Hh, h = bh % Hh;
  const int i0 = blockIdx.y * 64;
  const int t = threadIdx.x;
  const int tx = t & 15;
  const int ty = t >> 4;

  const float* cb = cbuf + (size_t)bh * (Nn + 1);
  const float* qbase = qkv + (size_t)b * Nn * 3 * Cc + h * Dd;
  const float* kbase = qbase + Cc;
  const float* vbase = qbase + 2 * Cc;

  #pragma unroll
  for (int r = 0; r < 4; r++) {
    int idx = t + r * 256;
    int row = idx >> 4, dq = (idx & 15) << 2;
    float4 q4 = *(const float4*)(qbase + (size_t)(i0 + row) * 3 * Cc + dq);
    QsT[(dq + 0) * 68 + row] = q4.x; QsT[(dq + 1) * 68 + row] = q4.y;
    QsT[(dq + 2) * 68 + row] = q4.z; QsT[(dq + 3) * 68 + row] = q4.w;
  }
  if (t < 64) { ci[t] = cb[i0 + t]; ci1[t] = cb[i0 + t + 1]; }

  float acc[4][4] = {};
  float rsum[4] = {};

  for (int jt = 0; jt < 16; jt++) {
    const int j0 = jt * 64;
    __syncthreads();
    #pragma unroll
    for (int r = 0; r < 4; r++) {
      int idx = t + r * 256;
      int row = idx >> 4, dq = (idx & 15) << 2;
      float4 k4 = *(const float4*)(kbase + (size_t)(j0 + row) * 3 * Cc + dq);
      KsT[(dq + 0) * 68 + row] = k4.x; KsT[(dq + 1) * 68 + row] = k4.y;
      KsT[(dq + 2) * 68 + row] = k4.z; KsT[(dq + 3) * 68 + row] = k4.w;
      float4 v4 = *(const float4*)(vbase + (size_t)(j0 + row) * 3 * Cc + dq);
      *(float4*)&Vs[row * 68 + dq] = v4;
    }
    if (t < 64) { cj[t] = cb[j0 + t]; cj1[t] = cb[j0 + t + 1]; }
    __syncthreads();

    float s[4][4] = {};
    #pragma unroll 16
    for (int d = 0; d < 64; d++) {
      float4 q4 = *(const float4*)&QsT[d * 68 + ty * 4];
      float4 k4 = *(const float4*)&KsT[d * 68 + tx * 4];
      OUTER4(s, q4, k4);
    }
    #pragma unroll
    for (int jj = 0; jj < 4; jj++) {
      const int jl = tx * 4 + jj;
      const int jg = j0 + jl;
      const float cjv = cj[jl], cj1v = cj1[jl];
      #pragma unroll
      for (int ii = 0; ii < 4; ii++) {
        const int il = ty * 4 + ii;
        const int ig = i0 + il;
        float arg = (jg < ig) ? (ci[il] - cjv) : ((jg > ig) ? (cj1v - ci1[il]) : 0.f);
        float w = s[ii][jj] * ATT_SCALE * __expf(arg);
        rsum[ii] += w;
        SsT[jl * 68 + il] = w;
      }
    }
    __syncthreads();

    #pragma unroll 8
    for (int j = 0; j < 64; j++) {
      float4 s4 = *(const float4*)&SsT[j * 68 + ty * 4];
      float4 v4 = *(const float4*)&Vs[j * 68 + tx * 4];
      OUTER4(acc, s4, v4);
    }
  }

  #pragma unroll
  for (int ii = 0; ii < 4; ii++) rs[(ty * 4 + ii) * 16 + tx] = rsum[ii];
  __syncthreads();
  #pragma unroll
  for (int ii = 0; ii < 4; ii++) {
    const int il = ty * 4 + ii;
    float tot = 0.f;
    #pragma unroll
    for (int g = 0; g < 16; g++) tot += rs[il * 16 + g];
    float inv = 1.f / (tot + 1e-6f);
    float4 o;
    o.x = acc[ii][0] * inv; o.y = acc[ii][1] * inv;
    o.z = acc[ii][2] * inv; o.w = acc[ii][3] * inv;
    *(float4*)&ao[((size_t)(b * Nn + i0 + il)) * Cc + h * Dd + tx * 4] = o;
  }
}

// ---------------- launch ----------------
extern "C" void kernel_launch(void* const* d_in, const int* in_sizes, int n_in,
                              void* d_out, int out_size)
{
  const float* x     = (const float*)d_in[0];
  const float* Wqkv  = (const float*)d_in[1];
  const float* Wa    = (const float*)d_in[2];
  const float* ba    = (const float*)d_in[3];
  const float* Wproj = (const float*)d_in[4];
  const float* bproj = (const float*)d_in[5];
  float* out = (float*)d_out;

  float *qkv, *cbuf, *aobuf;
  cudaGetSymbolAddress((void**)&qkv,   g_qkv);
  cudaGetSymbolAddress((void**)&cbuf,  g_c);
  cudaGetSymbolAddress((void**)&aobuf, g_ao);

  const int SMEM_ATTN = (4 * 64 * 68 + 4 * 64 + 64 * 16) * (int)sizeof(float); // 74752 B
  cudaFuncSetAttribute(attn_kernel, cudaFuncAttributeMaxDynamicSharedMemorySize, SMEM_ATTN);
  cudaFuncSetAttribute(gemm_mma, cudaFuncAttributeMaxDynamicSharedMemorySize, GSMEM);

  // 1) qkv = x @ Wqkv^T   [2048 x 2304]   (bf16 mma.sync, 3-pass split)
  gemm_mma<<<dim3(3 * Cc / 128, Bb * Nn / 128), 256, GSMEM>>>(x, Wqkv, nullptr, qkv, Bb * Nn, 3 * Cc, Cc);
  // 2) gate logits
  gate_logits<<<Bb * Nn / 8, 256>>>(x, Wa, ba);
  // 3) prefix-sum of log gates per (b,h)
  gate_scan<<<Bb * Hh, 1024>>>();
  // 4) q/k silu+0.5 + L2 norm, in place
  qk_norm<<<Bb * Nn, 256>>>();
  // 5) attention (fp32 — candidate for mma.sync next)
  attn_kernel<<<dim3(Bb * Hh, Nn / 64), 256, SMEM_ATTN>>>(qkv, cbuf, aobuf);
  // 6) out = ao @ Wproj^T + bproj   (bf16 mma.sync, 3-pass split)
  gemm_mma<<<dim3(Cc / 128, Bb * Nn / 128), 256, GSMEM>>>(aobuf, Wproj, bproj, out, Bb * Nn, Cc, Cc);
}

// round 4
// speedup vs baseline: 1.5802x; 1.0368x over previous
#include <cuda_runtime.h>
#include <cuda_bf16.h>
#include <math.h>
#include <cstdint>

#define Bb 2
#define Nn 1024
#define Cc 768
#define Hh 12
#define Dd 64
#define ATT_SCALE 0.125f   // D^-0.5

// ---------------- scratch (static device memory; no allocations) ----------------
__device__ float g_qkv[Bb * Nn * 3 * Cc];      // [b, n, s, h, d] contiguous = [2048, 2304]
__device__ float g_z  [Bb * Nn * Hh];          // gate logits
__device__ float g_c  [Bb * Hh * (Nn + 1)];    // prefix sums of log a
__device__ float g_ao [Bb * Nn * Cc];          // attention output [b, n, h, d]

__device__ __forceinline__ uint32_t smem_u32(const void* p) {
  uint32_t a;
  asm("{ .reg .u64 t; cvta.to.shared.u64 t, %1; cvt.u32.u64 %0, t; }" : "=r"(a) : "l"(p));
  return a;
}

#define LDSM4(R0, R1, R2, R3, addr) \
  asm volatile("ldmatrix.sync.aligned.m8n8.x4.shared.b16 {%0,%1,%2,%3}, [%4];" \
               : "=r"(R0), "=r"(R1), "=r"(R2), "=r"(R3) : "r"(addr))

#define MMA16816(C, A0, A1, A2, A3, B0, B1) \
  asm volatile("mma.sync.aligned.m16n8k16.row.col.f32.bf16.bf16.f32 " \
               "{%0,%1,%2,%3}, {%4,%5,%6,%7}, {%8,%9}, {%0,%1,%2,%3};" \
               : "+f"((C)[0]), "+f"((C)[1]), "+f"((C)[2]), "+f"((C)[3]) \
               : "r"(A0), "r"(A1), "r"(A2), "r"(A3), "r"(B0), "r"(B1))

// split fp32x8 -> bf16 hi/lo x8 (2-term split; dropped lo*lo ~ 2^-16 relative)
__device__ __forceinline__ void cvt8(const float4 a, const float4 b, uint4& hi, uint4& lo) {
  __nv_bfloat162 h; float2 f; __nv_bfloat162 l;
  h = __floats2bfloat162_rn(a.x, a.y); hi.x = *(uint32_t*)&h; f = __bfloat1622float2(h);
  l = __floats2bfloat162_rn(a.x - f.x, a.y - f.y); lo.x = *(uint32_t*)&l;
  h = __floats2bfloat162_rn(a.z, a.w); hi.y = *(uint32_t*)&h; f = __bfloat1622float2(h);
  l = __floats2bfloat162_rn(a.z - f.x, a.w - f.y); lo.y = *(uint32_t*)&l;
  h = __floats2bfloat162_rn(b.x, b.y); hi.z = *(uint32_t*)&h; f = __bfloat1622float2(h);
  l = __floats2bfloat162_rn(b.x - f.x, b.y - f.y); lo.z = *(uint32_t*)&l;
  h = __floats2bfloat162_rn(b.z, b.w); hi.w = *(uint32_t*)&h; f = __bfloat1622float2(h);
  l = __floats2bfloat162_rn(b.z - f.x, b.w - f.y); lo.w = *(uint32_t*)&l;
}

// ============ tensor-core GEMM (bf16 3-pass split): C[M,N] = A[M,K] @ B[N,K]^T (+bias) ======
#define GPITCH 80
#define GMAT   (128 * GPITCH)       // 10240
#define GSTAGE (2 * GMAT)           // 20480
#define GSMEM  (2 * GSTAGE)         // 40960

__global__ __launch_bounds__(256, 1) void gemm_mma(
    const float* __restrict__ A, const float* __restrict__ B,
    const float* __restrict__ bias, float* __restrict__ Cout,
    int M, int N, int K)
{
  extern __shared__ char smc[];
  const uint32_t sb = smem_u32(smc);
  const int tid = threadIdx.x, wid = tid >> 5, lane = tid & 31;
  const int m0 = blockIdx.y * 128, n0 = blockIdx.x * 128;
  const int wm = (wid & 1) * 64, wn = (wid >> 1) * 32;

  const int lrow = tid >> 1;
  const int lcol = (tid & 1) * 8;
  const float* Ag = A + (size_t)(m0 + lrow) * K + lcol;
  const float* Bg = B + (size_t)(n0 + lrow) * K + lcol;
  const uint32_t stA = sb + lrow * GPITCH + (lcol ? 16 : 0);   // hi bytes; lo at +32
  const uint32_t stB = stA + GMAT;

  const uint32_t aoff = (uint32_t)((wm + (lane & 15)) * GPITCH + ((lane >> 4) * 16));
  const uint32_t boff = (uint32_t)((wn + ((lane >> 4) << 3) + (lane & 7)) * GPITCH
                                   + (((lane >> 3) & 1) * 16)) + GMAT;

  float c[4][4][4] = {};
  const int NK = K / 16;

  float4 pa0, pa1, pb0, pb1;
  pa0 = *(const float4*)(Ag);     pa1 = *(const float4*)(Ag + 4);
  pb0 = *(const float4*)(Bg);     pb1 = *(const float4*)(Bg + 4);
  {
    uint4 hi, lo;
    cvt8(pa0, pa1, hi, lo);
    *(uint4*)(smc + (stA - sb))      = hi;
    *(uint4*)(smc + (stA - sb) + 32) = lo;
    cvt8(pb0, pb1, hi, lo);
    *(uint4*)(smc + (stB - sb))      = hi;
    *(uint4*)(smc + (stB - sb) + 32) = lo;
  }
  __syncthreads();

  for (int kc = 0; kc < NK; kc++) {
    const int s = kc & 1;
    if (kc + 1 < NK) {
      pa0 = *(const float4*)(Ag + (kc + 1) * 16);
      pa1 = *(const float4*)(Ag + (kc + 1) * 16 + 4);
      pb0 = *(const float4*)(Bg + (kc + 1) * 16);
      pb1 = *(const float4*)(Bg + (kc + 1) * 16 + 4);
    }

    const uint32_t stg = sb + s * GSTAGE;
    uint32_t ahi[4][4], alo[4][4], bhi[2][4], blo[2][4];
    #pragma unroll
    for (int mt = 0; mt < 4; mt++) {
      uint32_t ad = stg + aoff + mt * (16 * GPITCH);
      LDSM4(ahi[mt][0], ahi[mt][1], ahi[mt][2], ahi[mt][3], ad);
      LDSM4(alo[mt][0], alo[mt][1], alo[mt][2], alo[mt][3], ad + 32);
    }
    #pragma unroll
    for (int g = 0; g < 2; g++) {
      uint32_t bd = stg + boff + g * (16 * GPITCH);
      LDSM4(bhi[g][0], bhi[g][1], bhi[g][2], bhi[g][3], bd);
      LDSM4(blo[g][0], blo[g][1], blo[g][2], blo[g][3], bd + 32);
    }

    #pragma unroll
    for (int mt = 0; mt < 4; mt++) {
      #pragma unroll
      for (int nt = 0; nt < 4; nt++) {
        const int g = nt >> 1, q = (nt & 1) * 2;
        MMA16816(c[mt][nt], ahi[mt][0], ahi[mt][1], ahi[mt][2], ahi[mt][3], bhi[g][q], bhi[g][q + 1]);
        MMA16816(c[mt][nt], ahi[mt][0], ahi[mt][1], ahi[mt][2], ahi[mt][3], blo[g][q], blo[g][q + 1]);
        MMA16816(c[mt][nt], alo[mt][0], alo[mt][1], alo[mt][2], alo[mt][3], bhi[g][q], bhi[g][q + 1]);
      }
    }

    if (kc + 1 < NK) {
      const uint32_t dst = (stA - sb) + ((kc + 1) & 1) * GSTAGE;
      uint4 hi, lo;
      cvt8(pa0, pa1, hi, lo);
      *(uint4*)(smc + dst)      = hi;
      *(uint4*)(smc + dst + 32) = lo;
      cvt8(pb0, pb1, hi, lo);
      *(uint4*)(smc + dst + GMAT)      = hi;
      *(uint4*)(smc + dst + GMAT + 32) = lo;
    }
    __syncthreads();
  }

  #pragma unroll
  for (int mt = 0; mt < 4; mt++) {
    const int row = m0 + wm + mt * 16 + (lane >> 2);
    #pragma unroll
    for (int nt = 0; nt < 4; nt++) {
      const int col = n0 + wn + nt * 8 + (lane & 3) * 2;
      float bx = 0.f, by = 0.f;
      if (bias) { bx = __ldg(&bias[col]); by = __ldg(&bias[col + 1]); }
      *(float2*)&Cout[(size_t)row * N + col] =
          make_float2(c[mt][nt][0] + bx, c[mt][nt][1] + by);
      *(float2*)&Cout[(size_t)(row + 8) * N + col] =
          make_float2(c[mt][nt][2] + bx, c[mt][nt][3] + by);
    }
  }
}

// ---------------- gate logits ----------------
__global__ __launch_bounds__(256) void gate_logits(
    const float* __restrict__ x, const float* __restrict__ Wa, const float* __restrict__ ba)
{
  __shared__ float sW[Hh * Cc];   // 36 KB
  const int t = threadIdx.x;
  for (int i = t; i < Hh * Cc; i += 256) sW[i] = Wa[i];
  __syncthreads();

  const int warp = t >> 5, lane = t & 31;
  const int row = blockIdx.x * 8 + warp;
  const float* xr = x + (size_t)row * Cc;

  float acc[Hh] = {};
  for (int c0 = 0; c0 < Cc; c0 += 32) {
    float xv = xr[c0 + lane];
    #pragma unroll
    for (int h = 0; h < Hh; h++) acc[h] += xv * sW[h * Cc + c0 + lane];
  }
  #pragma unroll
  for (int h = 0; h < Hh; h++) {
    float v = acc[h];
    #pragma unroll
    for (int o = 16; o; o >>= 1) v += __shfl_xor_sync(0xffffffffu, v, o);
    if (lane == 0) g_z[(size_t)row * Hh + h] = v + ba[h];
  }
}

// ---------------- per-(b,h) scan ----------------
__global__ __launch_bounds__(1024) void gate_scan()
{
  __shared__ float sh[1024];
  const int bh = blockIdx.x;
  const int b = bh / Hh, h = bh % Hh;
  const int t = threadIdx.x;

  float la = 0.f;
  if (t > 0) {
    float z = g_z[((size_t)b * Nn + t) * Hh + h];
    float sp = (z > 15.f) ? z : log1pf(__expf(z));   // softplus
    la = -sp;
  }
  sh[t] = la;
  __syncthreads();
  #pragma unroll
  for (int off = 1; off < 1024; off <<= 1) {
    float v = (t >= off) ? sh[t - off] : 0.f;
    __syncthreads();
    sh[t] += v;
    __syncthreads();
  }
  float* cp = g_c + (size_t)bh * (Nn + 1);
  if (t == 0) cp[0] = 0.f;
  cp[t + 1] = sh[t];
}

// ---------------- q/k: silu(z)+0.5, L2-normalize ----------------
__global__ __launch_bounds__(256) void qk_norm()
{
  const int bn = blockIdx.x;
  const int warp = threadIdx.x >> 5, lane = threadIdx.x & 31;
  for (int task = warp; task < 2 * Hh; task += 8) {
    const int s = task & 1, h = task >> 1;
    float* p = g_qkv + (size_t)bn * 3 * Cc + s * Cc + h * Dd;
    float v0 = p[lane], v1 = p[lane + 32];
    float r0 = v0 / (1.f + __expf(-v0)) + 0.5f;
    float r1 = v1 / (1.f + __expf(-v1)) + 0.5f;
    float ss = r0 * r0 + r1 * r1;
    #pragma unroll
    for (int o = 16; o; o >>= 1) ss += __shfl_xor_sync(0xffffffffu, ss, o);
    float inv = rsqrtf(ss);
    p[lane] = r0 * inv;
    p[lane + 32] = r1 * inv;
  }
}

#define OUTER4(ACC, A4, B4) do { \
  ACC[0][0] += A4.x*B4.x; ACC[0][1] += A4.x*B4.y; ACC[0][2] += A4.x*B4.z; ACC[0][3] += A4.x*B4.w; \
  ACC[1][0] += A4.y*B4.x; ACC[1][1] += A4.y*B4.y; ACC[1][2] += A4.y*B4.z; ACC[1][3] += A4.y*B4.w; \
  ACC[2][0] += A4.z*B4.x; ACC[2][1] += A4.z*B4.y; ACC[2][2] += A4.z*B4.z; ACC[2][3] += A4.z*B4.w; \
  ACC[3][0] += A4.w*B4.x; ACC[3][1] += A4.w*B4.y; ACC[3][2] += A4.w*B4.z; ACC[3][3] += A4.w*B4.w; \
} while (0)

// ---------------- attention with factorized decay mask ----------------
// Tile classification (i-block = by, j-tile = jt, both 64-wide):
//  jt < by (all j<i):  w = s*SCALE * Fi[i] * G[j],  Fi=exp(ci-c[i0])<=1, G=exp(c[i0]-cj)<=1
//  jt > by (all j>i):  w = s*SCALE * H[i] * G[j],   G=exp(c[j+1]-c[j0])<=1, H=exp(c[j0]-c[i+1])<=1
//  jt == by: exact per-element exp (4096 exps)
__global__ __launch_bounds__(256) void attn_kernel(
    const float* __restrict__ qkv, const float* __restrict__ cbuf, float* __restrict__ ao)
{
  extern __shared__ float sm[];
  float* QsT = sm;                 // [d][i] 64x68
  float* KsT = QsT + 64 * 68;      // [d][j] 64x68
  float* Vs  = KsT + 64 * 68;      // [j][d] 64x68
  float* SsT = Vs  + 64 * 68;      // [j][i] 64x68
  float* ci  = SsT + 64 * 68;      // 64
  float* ci1 = ci  + 64;           // 64
  float* cj  = ci1 + 64;           // 64
  float* cj1 = cj  + 64;           // 64
  float* rs  = cj1 + 64;           // [i][16] rowsum partials
  float* sFi = rs  + 64 * 16;      // 64 forward row factors
  float* sG  = sFi + 64;           // 64 per-tile column factors
  float* sH  = sG  + 64;           // 64 per-tile backward row factors

  const int bh = blockIdx.x;
  const int b = bh / Hh, h = bh % Hh;
  const int by = blockIdx.y;
  const int i0 = by * 64;
  const int t = threadIdx.x;
  const int tx = t & 15;
  const int ty = t >> 4;

  const float* cb = cbuf + (size_t)bh * (Nn + 1);
  const float* qbase = qkv + (size_t)b * Nn * 3 * Cc + h * Dd;
  const float* kbase = qbase + Cc;
  const float* vbase = qbase + 2 * Cc;

  #pragma unroll
  for (int r = 0; r < 4; r++) {
    int idx = t + r * 256;
    int row = idx >> 4, dq = (idx & 15) << 2;
    float4 q4 = *(const float4*)(qbase + (size_t)(i0 + row) * 3 * Cc + dq);
    QsT[(dq + 0) * 68 + row] = q4.x; QsT[(dq + 1) * 68 + row] = q4.y;
    QsT[(dq + 2) * 68 + row] = q4.z; QsT[(dq + 3) * 68 + row] = q4.w;
  }
  if (t < 64) {
    ci[t]  = cb[i0 + t];
    ci1[t] = cb[i0 + t + 1];
    sFi[t] = __expf(cb[i0 + t] - cb[i0]);          // <= 1
  }

  float acc[4][4] = {};
  float rsum[4] = {};

  for (int jt = 0; jt < 16; jt++) {
    const int j0 = jt * 64;
    __syncthreads();
    #pragma unroll
    for (int r = 0; r < 4; r++) {
      int idx = t + r * 256;
      int row = idx >> 4, dq = (idx & 15) << 2;
      float4 k4 = *(const float4*)(kbase + (size_t)(j0 + row) * 3 * Cc + dq);
      KsT[(dq + 0) * 68 + row] = k4.x; KsT[(dq + 1) * 68 + row] = k4.y;
      KsT[(dq + 2) * 68 + row] = k4.z; KsT[(dq + 3) * 68 + row] = k4.w;
      float4 v4 = *(const float4*)(vbase + (size_t)(j0 + row) * 3 * Cc + dq);
      *(float4*)&Vs[row * 68 + dq] = v4;
    }
    if (jt == by) {
      if (t < 64) { cj[t] = cb[j0 + t]; cj1[t] = cb[j0 + t + 1]; }
    } else if (jt < by) {
      if (t < 64) sG[t] = __expf(cb[i0] - cb[j0 + t]);          // <= 1
    } else {
      if (t < 64)       sG[t]      = __expf(cb[j0 + t + 1] - cb[j0]);  // <= 1
      else if (t < 128) sH[t - 64] = __expf(cb[j0] - cb[i0 + (t - 64) + 1]); // <= 1
    }
    __syncthreads();

    // phase A: scores
    float s[4][4] = {};
    #pragma unroll 16
    for (int d = 0; d < 64; d++) {
      float4 q4 = *(const float4*)&QsT[d * 68 + ty * 4];
      float4 k4 = *(const float4*)&KsT[d * 68 + tx * 4];
      OUTER4(s, q4, k4);
    }

    if (jt == by) {
      // exact diagonal tile
      #pragma unroll
      for (int jj = 0; jj < 4; jj++) {
        const int jl = tx * 4 + jj;
        const int jg = j0 + jl;
        const float cjv = cj[jl], cj1v = cj1[jl];
        #pragma unroll
        for (int ii = 0; ii < 4; ii++) {
          const int il = ty * 4 + ii;
          const int ig = i0 + il;
          float arg = (jg < ig) ? (ci[il] - cjv) : ((jg > ig) ? (cj1v - ci1[il]) : 0.f);
          float w = s[ii][jj] * ATT_SCALE * __expf(arg);
          rsum[ii] += w;
          SsT[jl * 68 + il] = w;
        }
      }
    } else {
      const float* rf = (jt < by) ? sFi : sH;
      float g[4], rsc[4];
      #pragma unroll
      for (int jj = 0; jj < 4; jj++) g[jj] = sG[tx * 4 + jj];
      #pragma unroll
      for (int ii = 0; ii < 4; ii++) rsc[ii] = ATT_SCALE * rf[ty * 4 + ii];
      #pragma unroll
      for (int jj = 0; jj < 4; jj++) {
        const int jl = tx * 4 + jj;
        #pragma unroll
        for (int ii = 0; ii < 4; ii++) {
          float w = s[ii][jj] * rsc[ii] * g[jj];
          rsum[ii] += w;
          SsT[jl * 68 + (ty * 4 + ii)] = w;
        }
      }
    }
    __syncthreads();

    // phase B: acc += S^T . V
    #pragma unroll 8
    for (int j = 0; j < 64; j++) {
      float4 s4 = *(const float4*)&SsT[j * 68 + ty * 4];
      float4 v4 = *(const float4*)&Vs[j * 68 + tx * 4];
      OUTER4(acc, s4, v4);
    }
  }

  #pragma unroll
  for (int ii = 0; ii < 4; ii++) rs[(ty * 4 + ii) * 16 + tx] = rsum[ii];
  __syncthreads();
  #pragma unroll
  for (int ii = 0; ii < 4; ii++) {
    const int il = ty * 4 + ii;
    float tot = 0.f;
    #pragma unroll
    for (int g = 0; g < 16; g++) tot += rs[il * 16 + g];
    float inv = 1.f / (tot + 1e-6f);
    float4 o;
    o.x = acc[ii][0] * inv; o.y = acc[ii][1] * inv;
    o.z = acc[ii][2] * inv; o.w = acc[ii][3] * inv;
    *(float4*)&ao[((size_t)(b * Nn + i0 + il)) * Cc + h * Dd + tx * 4] = o;
  }
}

// ---------------- launch ----------------
extern "C" void kernel_launch(void* const* d_in, const int* in_sizes, int n_in,
                              void* d_out, int out_size)
{
  const float* x     = (const float*)d_in[0];
  const float* Wqkv  = (const float*)d_in[1];
  const float* Wa    = (const float*)d_in[2];
  const float* ba    = (const float*)d_in[3];
  const float* Wproj = (const float*)d_in[4];
  const float* bproj = (const float*)d_in[5];
  float* out = (float*)d_out;

  float *qkv, *cbuf, *aobuf;
  cudaGetSymbolAddress((void**)&qkv,   g_qkv);
  cudaGetSymbolAddress((void**)&cbuf,  g_c);
  cudaGetSymbolAddress((void**)&aobuf, g_ao);

  const int SMEM_ATTN = (4 * 64 * 68 + 4 * 64 + 64 * 16 + 3 * 64) * (int)sizeof(float); // 75520 B
  cudaFuncSetAttribute(attn_kernel, cudaFuncAttributeMaxDynamicSharedMemorySize, SMEM_ATTN);
  cudaFuncSetAttribute(gemm_mma, cudaFuncAttributeMaxDynamicSharedMemorySize, GSMEM);

  // 1) qkv = x @ Wqkv^T (bf16 mma, 3-pass split)
  gemm_mma<<<dim3(3 * Cc / 128, Bb * Nn / 128), 256, GSMEM>>>(x, Wqkv, nullptr, qkv, Bb * Nn, 3 * Cc, Cc);
  // 2) gate logits
  gate_logits<<<Bb * Nn / 8, 256>>>(x, Wa, ba);
  // 3) prefix-sum of log gates per (b,h)
  gate_scan<<<Bb * Hh, 1024>>>();
  // 4) q/k silu+0.5 + L2 norm, in place
  qk_norm<<<Bb * Nn, 256>>>();
  // 5) attention (factorized decay mask)
  attn_kernel<<<dim3(Bb * Hh, Nn / 64), 256, SMEM_ATTN>>>(qkv, cbuf, aobuf);
  // 6) out = ao @ Wproj^T + bproj (bf16 mma, 3-pass split)
  gemm_mma<<<dim3(Cc / 128, Bb * Nn / 128), 256, GSMEM>>>(aobuf, Wproj, bproj, out, Bb * Nn, Cc, Cc);
}

// round 5
// speedup vs baseline: 2.2130x; 1.4005x over previous
#include <cuda_runtime.h>
#include <cuda_bf16.h>
#include <math.h>
#include <cstdint>

#define Bb 2
#define Nn 1024
#define Cc 768
#define Hh 12
#define Dd 64
#define ATT_SCALE 0.125f   // D^-0.5

// ---------------- scratch (static device memory; no allocations) ----------------
__device__ float g_qkv[Bb * Nn * 3 * Cc];      // [b, n, s, h, d] contiguous = [2048, 2304]
__device__ float g_z  [Bb * Nn * Hh];          // gate logits
__device__ float g_c  [Bb * Hh * (Nn + 1)];    // prefix sums of log a
__device__ float g_ao [Bb * Nn * Cc];          // attention output [b, n, h, d]

__device__ __forceinline__ uint32_t smem_u32(const void* p) {
  uint32_t a;
  asm("{ .reg .u64 t; cvta.to.shared.u64 t, %1; cvt.u32.u64 %0, t; }" : "=r"(a) : "l"(p));
  return a;
}

#define LDSM4(R0, R1, R2, R3, addr) \
  asm volatile("ldmatrix.sync.aligned.m8n8.x4.shared.b16 {%0,%1,%2,%3}, [%4];" \
               : "=r"(R0), "=r"(R1), "=r"(R2), "=r"(R3) : "r"(addr))

#define MMA16816(C, A0, A1, A2, A3, B0, B1) \
  asm volatile("mma.sync.aligned.m16n8k16.row.col.f32.bf16.bf16.f32 " \
               "{%0,%1,%2,%3}, {%4,%5,%6,%7}, {%8,%9}, {%0,%1,%2,%3};" \
               : "+f"((C)[0]), "+f"((C)[1]), "+f"((C)[2]), "+f"((C)[3]) \
               : "r"(A0), "r"(A1), "r"(A2), "r"(A3), "r"(B0), "r"(B1))

// split fp32x8 -> bf16 hi/lo x8 (2-term split; dropped lo*lo ~ 2^-16 relative)
__device__ __forceinline__ void cvt8(const float4 a, const float4 b, uint4& hi, uint4& lo) {
  __nv_bfloat162 h; float2 f; __nv_bfloat162 l;
  h = __floats2bfloat162_rn(a.x, a.y); hi.x = *(uint32_t*)&h; f = __bfloat1622float2(h);
  l = __floats2bfloat162_rn(a.x - f.x, a.y - f.y); lo.x = *(uint32_t*)&l;
  h = __floats2bfloat162_rn(a.z, a.w); hi.y = *(uint32_t*)&h; f = __bfloat1622float2(h);
  l = __floats2bfloat162_rn(a.z - f.x, a.w - f.y); lo.y = *(uint32_t*)&l;
  h = __floats2bfloat162_rn(b.x, b.y); hi.z = *(uint32_t*)&h; f = __bfloat1622float2(h);
  l = __floats2bfloat162_rn(b.x - f.x, b.y - f.y); lo.z = *(uint32_t*)&l;
  h = __floats2bfloat162_rn(b.z, b.w); hi.w = *(uint32_t*)&h; f = __bfloat1622float2(h);
  l = __floats2bfloat162_rn(b.z - f.x, b.w - f.y); lo.w = *(uint32_t*)&l;
}

// ============ tensor-core GEMM (bf16 3-pass split): C[M,N] = A[M,K] @ B[N,K]^T (+bias) ======
#define GPITCH 80
#define GMAT   (128 * GPITCH)       // 10240
#define GSTAGE (2 * GMAT)           // 20480
#define GSMEM  (2 * GSTAGE)         // 40960

__global__ __launch_bounds__(256, 1) void gemm_mma(
    const float* __restrict__ A, const float* __restrict__ B,
    const float* __restrict__ bias, float* __restrict__ Cout,
    int M, int N, int K)
{
  extern __shared__ char smc[];
  const uint32_t sb = smem_u32(smc);
  const int tid = threadIdx.x, wid = tid >> 5, lane = tid & 31;
  const int m0 = blockIdx.y * 128, n0 = blockIdx.x * 128;
  const int wm = (wid & 1) * 64, wn = (wid >> 1) * 32;

  const int lrow = tid >> 1;
  const int lcol = (tid & 1) * 8;
  const float* Ag = A + (size_t)(m0 + lrow) * K + lcol;
  const float* Bg = B + (size_t)(n0 + lrow) * K + lcol;
  const uint32_t stA = sb + lrow * GPITCH + (lcol ? 16 : 0);
  const uint32_t stB = stA + GMAT;

  const uint32_t aoff = (uint32_t)((wm + (lane & 15)) * GPITCH + ((lane >> 4) * 16));
  const uint32_t boff = (uint32_t)((wn + ((lane >> 4) << 3) + (lane & 7)) * GPITCH
                                   + (((lane >> 3) & 1) * 16)) + GMAT;

  float c[4][4][4] = {};
  const int NK = K / 16;

  float4 pa0, pa1, pb0, pb1;
  pa0 = *(const float4*)(Ag);     pa1 = *(const float4*)(Ag + 4);
  pb0 = *(const float4*)(Bg);     pb1 = *(const float4*)(Bg + 4);
  {
    uint4 hi, lo;
    cvt8(pa0, pa1, hi, lo);
    *(uint4*)(smc + (stA - sb))      = hi;
    *(uint4*)(smc + (stA - sb) + 32) = lo;
    cvt8(pb0, pb1, hi, lo);
    *(uint4*)(smc + (stB - sb))      = hi;
    *(uint4*)(smc + (stB - sb) + 32) = lo;
  }
  __syncthreads();

  for (int kc = 0; kc < NK; kc++) {
    const int s = kc & 1;
    if (kc + 1 < NK) {
      pa0 = *(const float4*)(Ag + (kc + 1) * 16);
      pa1 = *(const float4*)(Ag + (kc + 1) * 16 + 4);
      pb0 = *(const float4*)(Bg + (kc + 1) * 16);
      pb1 = *(const float4*)(Bg + (kc + 1) * 16 + 4);
    }

    const uint32_t stg = sb + s * GSTAGE;
    uint32_t ahi[4][4], alo[4][4], bhi[2][4], blo[2][4];
    #pragma unroll
    for (int mt = 0; mt < 4; mt++) {
      uint32_t ad = stg + aoff + mt * (16 * GPITCH);
      LDSM4(ahi[mt][0], ahi[mt][1], ahi[mt][2], ahi[mt][3], ad);
      LDSM4(alo[mt][0], alo[mt][1], alo[mt][2], alo[mt][3], ad + 32);
    }
    #pragma unroll
    for (int g = 0; g < 2; g++) {
      uint32_t bd = stg + boff + g * (16 * GPITCH);
      LDSM4(bhi[g][0], bhi[g][1], bhi[g][2], bhi[g][3], bd);
      LDSM4(blo[g][0], blo[g][1], blo[g][2], blo[g][3], bd + 32);
    }

    #pragma unroll
    for (int mt = 0; mt < 4; mt++) {
      #pragma unroll
      for (int nt = 0; nt < 4; nt++) {
        const int g = nt >> 1, q = (nt & 1) * 2;
        MMA16816(c[mt][nt], ahi[mt][0], ahi[mt][1], ahi[mt][2], ahi[mt][3], bhi[g][q], bhi[g][q + 1]);
        MMA16816(c[mt][nt], ahi[mt][0], ahi[mt][1], ahi[mt][2], ahi[mt][3], blo[g][q], blo[g][q + 1]);
        MMA16816(c[mt][nt], alo[mt][0], alo[mt][1], alo[mt][2], alo[mt][3], bhi[g][q], bhi[g][q + 1]);
      }
    }

    if (kc + 1 < NK) {
      const uint32_t dst = (stA - sb) + ((kc + 1) & 1) * GSTAGE;
      uint4 hi, lo;
      cvt8(pa0, pa1, hi, lo);
      *(uint4*)(smc + dst)      = hi;
      *(uint4*)(smc + dst + 32) = lo;
      cvt8(pb0, pb1, hi, lo);
      *(uint4*)(smc + dst + GMAT)      = hi;
      *(uint4*)(smc + dst + GMAT + 32) = lo;
    }
    __syncthreads();
  }

  #pragma unroll
  for (int mt = 0; mt < 4; mt++) {
    const int row = m0 + wm + mt * 16 + (lane >> 2);
    #pragma unroll
    for (int nt = 0; nt < 4; nt++) {
      const int col = n0 + wn + nt * 8 + (lane & 3) * 2;
      float bx = 0.f, by = 0.f;
      if (bias) { bx = __ldg(&bias[col]); by = __ldg(&bias[col + 1]); }
      *(float2*)&Cout[(size_t)row * N + col] =
          make_float2(c[mt][nt][0] + bx, c[mt][nt][1] + by);
      *(float2*)&Cout[(size_t)(row + 8) * N + col] =
          make_float2(c[mt][nt][2] + bx, c[mt][nt][3] + by);
    }
  }
}

// ---------------- gate logits ----------------
__global__ __launch_bounds__(256) void gate_logits(
    const float* __restrict__ x, const float* __restrict__ Wa, const float* __restrict__ ba)
{
  __shared__ float sW[Hh * Cc];   // 36 KB
  const int t = threadIdx.x;
  for (int i = t; i < Hh * Cc; i += 256) sW[i] = Wa[i];
  __syncthreads();

  const int warp = t >> 5, lane = t & 31;
  const int row = blockIdx.x * 8 + warp;
  const float* xr = x + (size_t)row * Cc;

  float acc[Hh] = {};
  for (int c0 = 0; c0 < Cc; c0 += 32) {
    float xv = xr[c0 + lane];
    #pragma unroll
    for (int h = 0; h < Hh; h++) acc[h] += xv * sW[h * Cc + c0 + lane];
  }
  #pragma unroll
  for (int h = 0; h < Hh; h++) {
    float v = acc[h];
    #pragma unroll
    for (int o = 16; o; o >>= 1) v += __shfl_xor_sync(0xffffffffu, v, o);
    if (lane == 0) g_z[(size_t)row * Hh + h] = v + ba[h];
  }
}

// ---------------- per-(b,h) scan ----------------
__global__ __launch_bounds__(1024) void gate_scan()
{
  __shared__ float sh[1024];
  const int bh = blockIdx.x;
  const int b = bh / Hh, h = bh % Hh;
  const int t = threadIdx.x;

  float la = 0.f;
  if (t > 0) {
    float z = g_z[((size_t)b * Nn + t) * Hh + h];
    float sp = (z > 15.f) ? z : log1pf(__expf(z));   // softplus
    la = -sp;
  }
  sh[t] = la;
  __syncthreads();
  #pragma unroll
  for (int off = 1; off < 1024; off <<= 1) {
    float v = (t >= off) ? sh[t - off] : 0.f;
    __syncthreads();
    sh[t] += v;
    __syncthreads();
  }
  float* cp = g_c + (size_t)bh * (Nn + 1);
  if (t == 0) cp[0] = 0.f;
  cp[t + 1] = sh[t];
}

// ---------------- q/k: silu(z)+0.5, L2-normalize ----------------
__global__ __launch_bounds__(256) void qk_norm()
{
  const int bn = blockIdx.x;
  const int warp = threadIdx.x >> 5, lane = threadIdx.x & 31;
  for (int task = warp; task < 2 * Hh; task += 8) {
    const int s = task & 1, h = task >> 1;
    float* p = g_qkv + (size_t)bn * 3 * Cc + s * Cc + h * Dd;
    float v0 = p[lane], v1 = p[lane + 32];
    float r0 = v0 / (1.f + __expf(-v0)) + 0.5f;
    float r1 = v1 / (1.f + __expf(-v1)) + 0.5f;
    float ss = r0 * r0 + r1 * r1;
    #pragma unroll
    for (int o = 16; o; o >>= 1) ss += __shfl_xor_sync(0xffffffffu, ss, o);
    float inv = rsqrtf(ss);
    p[lane] = r0 * inv;
    p[lane + 32] = r1 * inv;
  }
}

// ================= attention on tensor cores (bf16 3-pass) ======================
// i-block 64, stream 16 j-tiles of 64. SMEM matrices: 64 rows x pitch 144B.
//  Q [i][d] (A-layout), K [j][d] (B-layout), VT [d][j] (B-layout for S.V),
//  S [i][j] (A-layout for S.V). All split hi/lo.
#define APITCH 144
#define AMAT   (64 * APITCH)   // 9216
// byte offsets
#define O_QHI  0
#define O_QLO  (O_QHI + AMAT)
#define O_KHI  (O_QLO + AMAT)
#define O_KLO  (O_KHI + AMAT)
#define O_VTHI (O_KLO + AMAT)
#define O_VTLO (O_VTHI + AMAT)
#define O_SHI  (O_VTLO + AMAT)
#define O_SLO  (O_SHI + AMAT)
#define O_CI   (O_SLO + AMAT)          // 64 f
#define O_CI1  (O_CI  + 256)
#define O_CJ   (O_CI1 + 256)
#define O_CJ1  (O_CJ  + 256)
#define O_FI   (O_CJ1 + 256)
#define O_G    (O_FI  + 256)
#define O_H    (O_G   + 256)
#define O_RS   (O_H   + 256)           // 64 x 8 f
#define ASMEM  (O_RS + 64 * 8 * 4)     // 77568

__global__ __launch_bounds__(256) void attn_kernel(
    const float* __restrict__ qkv, const float* __restrict__ cbuf, float* __restrict__ ao)
{
  extern __shared__ char smc[];
  const uint32_t sb = smem_u32(smc);
  float* ci  = (float*)(smc + O_CI);
  float* ci1 = (float*)(smc + O_CI1);
  float* cj  = (float*)(smc + O_CJ);
  float* cj1 = (float*)(smc + O_CJ1);
  float* sFi = (float*)(smc + O_FI);
  float* sG  = (float*)(smc + O_G);
  float* sH  = (float*)(smc + O_H);
  float* rs  = (float*)(smc + O_RS);

  const int bh = blockIdx.x;
  const int b = bh / Hh, h = bh % Hh;
  const int by = blockIdx.y;
  const int i0 = by * 64;
  const int tid = threadIdx.x, wid = tid >> 5, lane = tid & 31;
  const int wm = (wid & 3) * 16;        // S/out row group
  const int wn = (wid >> 2) * 32;       // S col group (phase A) / d col group (phase B)

  const float* cb = cbuf + (size_t)bh * (Nn + 1);
  const float* qbase = qkv + (size_t)b * Nn * 3 * Cc + h * Dd;
  const float* kbase = qbase + Cc;
  const float* vbase = qbase + 2 * Cc;

  // loader assignment: thread -> row (0..63), quarter q (16 floats)
  const int lrow = tid >> 2, lq = tid & 3;

  // stage Q (once): [i][d] hi/lo
  {
    const float* src = qbase + (size_t)(i0 + lrow) * 3 * Cc + lq * 16;
    float4 f0 = *(const float4*)(src);
    float4 f1 = *(const float4*)(src + 4);
    float4 f2 = *(const float4*)(src + 8);
    float4 f3 = *(const float4*)(src + 12);
    uint4 hi, lo;
    cvt8(f0, f1, hi, lo);
    *(uint4*)(smc + O_QHI + lrow * APITCH + lq * 32)      = hi;
    *(uint4*)(smc + O_QLO + lrow * APITCH + lq * 32)      = lo;
    cvt8(f2, f3, hi, lo);
    *(uint4*)(smc + O_QHI + lrow * APITCH + lq * 32 + 16) = hi;
    *(uint4*)(smc + O_QLO + lrow * APITCH + lq * 32 + 16) = lo;
  }
  if (tid < 64) {
    ci[tid]  = cb[i0 + tid];
    ci1[tid] = cb[i0 + tid + 1];
    sFi[tid] = __expf(cb[i0 + tid] - cb[i0]);   // <= 1
  }
  __syncthreads();

  // hoisted Q frags (A operand), 4 k-steps over d
  const uint32_t aoff = (uint32_t)((wm + (lane & 15)) * APITCH + ((lane >> 4) * 16));
  uint32_t qh[4][4], ql[4][4];
  #pragma unroll
  for (int k = 0; k < 4; k++) {
    uint32_t ad = sb + O_QHI + aoff + k * 32;
    LDSM4(qh[k][0], qh[k][1], qh[k][2], qh[k][3], ad);
    LDSM4(ql[k][0], ql[k][1], ql[k][2], ql[k][3], ad + AMAT);
  }

  // B-operand frag base (rows = n dim), reused for K and VT
  const uint32_t boff = (uint32_t)((wn + ((lane >> 4) << 3) + (lane & 7)) * APITCH
                                   + (((lane >> 3) & 1) * 16));

  float acc[4][4] = {};     // out frags [d-tile][4]
  float rsum0 = 0.f, rsum1 = 0.f;

  for (int jt = 0; jt < 16; jt++) {
    const int j0 = jt * 64;
    __syncthreads();   // previous tile done with K/VT/S

    // stage K [j][d] hi/lo
    {
      const float* src = kbase + (size_t)(j0 + lrow) * 3 * Cc + lq * 16;
      float4 f0 = *(const float4*)(src);
      float4 f1 = *(const float4*)(src + 4);
      float4 f2 = *(const float4*)(src + 8);
      float4 f3 = *(const float4*)(src + 12);
      uint4 hi, lo;
      cvt8(f0, f1, hi, lo);
      *(uint4*)(smc + O_KHI + lrow * APITCH + lq * 32)      = hi;
      *(uint4*)(smc + O_KLO + lrow * APITCH + lq * 32)      = lo;
      cvt8(f2, f3, hi, lo);
      *(uint4*)(smc + O_KHI + lrow * APITCH + lq * 32 + 16) = hi;
      *(uint4*)(smc + O_KLO + lrow * APITCH + lq * 32 + 16) = lo;
    }
    // stage V transposed: VT[d][j] hi/lo (scatter bf16 stores)
    {
      const float* src = vbase + (size_t)(j0 + lrow) * 3 * Cc + lq * 16;
      __nv_bfloat16* vh = (__nv_bfloat16*)(smc + O_VTHI);
      __nv_bfloat16* vl = (__nv_bfloat16*)(smc + O_VTLO);
      #pragma unroll
      for (int i = 0; i < 16; i++) {
        float v = src[i];
        __nv_bfloat16 hb = __float2bfloat16(v);
        __nv_bfloat16 lb = __float2bfloat16(v - __bfloat162float(hb));
        const int d = lq * 16 + i;
        vh[(d * APITCH) / 2 + lrow] = hb;
        vl[(d * APITCH) / 2 + lrow] = lb;
      }
    }
    // per-tile mask factors
    if (jt == by) {
      if (tid < 64) { cj[tid] = cb[j0 + tid]; cj1[tid] = cb[j0 + tid + 1]; }
    } else if (jt < by) {
      if (tid < 64) sG[tid] = __expf(cb[i0] - cb[j0 + tid]);
    } else {
      if (tid < 64)        sG[tid]       = __expf(cb[j0 + tid + 1] - cb[j0]);
      else if (tid < 128)  sH[tid - 64]  = __expf(cb[j0] - cb[i0 + (tid - 64) + 1]);
    }
    __syncthreads();

    // ---- phase A: S = Q.K^T (3-pass) ----
    float s[4][4] = {};
    #pragma unroll
    for (int k = 0; k < 4; k++) {
      uint32_t bd0 = sb + O_KHI + boff + k * 32;
      uint32_t bd1 = bd0 + 16 * APITCH;
      uint32_t kh0[4], kl0[4], kh1[4], kl1[4];
      LDSM4(kh0[0], kh0[1], kh0[2], kh0[3], bd0);
      LDSM4(kl0[0], kl0[1], kl0[2], kl0[3], bd0 + AMAT);
      LDSM4(kh1[0], kh1[1], kh1[2], kh1[3], bd1);
      LDSM4(kl1[0], kl1[1], kl1[2], kl1[3], bd1 + AMAT);
      #pragma unroll
      for (int nt = 0; nt < 4; nt++) {
        const uint32_t* KH = (nt < 2) ? kh0 : kh1;
        const uint32_t* KL = (nt < 2) ? kl0 : kl1;
        const int q = (nt & 1) * 2;
        MMA16816(s[nt], qh[k][0], qh[k][1], qh[k][2], qh[k][3], KH[q], KH[q + 1]);
        MMA16816(s[nt], qh[k][0], qh[k][1], qh[k][2], qh[k][3], KL[q], KL[q + 1]);
        MMA16816(s[nt], ql[k][0], ql[k][1], ql[k][2], ql[k][3], KH[q], KH[q + 1]);
      }
    }

    // ---- mask + rowsum + store S (bf16 hi/lo) ----
    const int r0l = wm + (lane >> 2);          // local i of frag rows 0/1
    const int r1l = r0l + 8;
    if (jt == by) {
      #pragma unroll
      for (int nt = 0; nt < 4; nt++) {
        const int jl = wn + nt * 8 + (lane & 3) * 2;
        #pragma unroll
        for (int e = 0; e < 4; e++) {
          const int il = (e < 2) ? r0l : r1l;
          const int jj = jl + (e & 1);
          const int ig = i0 + il, jg = j0 + jj;
          float arg = (jg < ig) ? (ci[il] - cj[jj]) : ((jg > ig) ? (cj1[jj] - ci1[il]) : 0.f);
          s[nt][e] = s[nt][e] * ATT_SCALE * __expf(arg);
        }
      }
    } else {
      const float* rf = (jt < by) ? sFi : sH;
      const float f0 = ATT_SCALE * rf[r0l];
      const float f1 = ATT_SCALE * rf[r1l];
      #pragma unroll
      for (int nt = 0; nt < 4; nt++) {
        const int jl = wn + nt * 8 + (lane & 3) * 2;
        const float g0 = sG[jl], g1 = sG[jl + 1];
        s[nt][0] *= f0 * g0; s[nt][1] *= f0 * g1;
        s[nt][2] *= f1 * g0; s[nt][3] *= f1 * g1;
      }
    }
    #pragma unroll
    for (int nt = 0; nt < 4; nt++) {
      rsum0 += s[nt][0] + s[nt][1];
      rsum1 += s[nt][2] + s[nt][3];
      const int jl = wn + nt * 8 + (lane & 3) * 2;
      __nv_bfloat162 h0 = __floats2bfloat162_rn(s[nt][0], s[nt][1]);
      float2 hf0 = __bfloat1622float2(h0);
      __nv_bfloat162 l0 = __floats2bfloat162_rn(s[nt][0] - hf0.x, s[nt][1] - hf0.y);
      __nv_bfloat162 h1 = __floats2bfloat162_rn(s[nt][2], s[nt][3]);
      float2 hf1 = __bfloat1622float2(h1);
      __nv_bfloat162 l1 = __floats2bfloat162_rn(s[nt][2] - hf1.x, s[nt][3] - hf1.y);
      *(uint32_t*)(smc + O_SHI + r0l * APITCH + jl * 2) = *(uint32_t*)&h0;
      *(uint32_t*)(smc + O_SLO + r0l * APITCH + jl * 2) = *(uint32_t*)&l0;
      *(uint32_t*)(smc + O_SHI + r1l * APITCH + jl * 2) = *(uint32_t*)&h1;
      *(uint32_t*)(smc + O_SLO + r1l * APITCH + jl * 2) = *(uint32_t*)&l1;
    }
    __syncthreads();

    // ---- phase B: acc += S.V (3-pass), k = j dim ----
    #pragma unroll
    for (int k = 0; k < 4; k++) {
      uint32_t ad = sb + O_SHI + aoff + k * 32;
      uint32_t sh4[4], sl4[4];
      LDSM4(sh4[0], sh4[1], sh4[2], sh4[3], ad);
      LDSM4(sl4[0], sl4[1], sl4[2], sl4[3], ad + AMAT);
      uint32_t bd0 = sb + O_VTHI + boff + k * 32;
      uint32_t bd1 = bd0 + 16 * APITCH;
      uint32_t vh0[4], vl0[4], vh1[4], vl1[4];
      LDSM4(vh0[0], vh0[1], vh0[2], vh0[3], bd0);
      LDSM4(vl0[0], vl0[1], vl0[2], vl0[3], bd0 + AMAT);
      LDSM4(vh1[0], vh1[1], vh1[2], vh1[3], bd1);
      LDSM4(vl1[0], vl1[1], vl1[2], vl1[3], bd1 + AMAT);
      #pragma unroll
      for (int nt = 0; nt < 4; nt++) {
        const uint32_t* VH = (nt < 2) ? vh0 : vh1;
        const uint32_t* VL = (nt < 2) ? vl0 : vl1;
        const int q = (nt & 1) * 2;
        MMA16816(acc[nt], sh4[0], sh4[1], sh4[2], sh4[3], VH[q], VH[q + 1]);
        MMA16816(acc[nt], sh4[0], sh4[1], sh4[2], sh4[3], VL[q], VL[q + 1]);
        MMA16816(acc[nt], sl4[0], sl4[1], sl4[2], sl4[3], VH[q], VH[q + 1]);
      }
    }
  }

  // ---- rowsum reduce + normalize + write ----
  __syncthreads();
  {
    const int r0l = wm + (lane >> 2);
    const int slot = (wid >> 2) * 4 + (lane & 3);
    rs[r0l * 8 + slot]       = rsum0;
    rs[(r0l + 8) * 8 + slot] = rsum1;
  }
  __syncthreads();
  {
    const int r0l = wm + (lane >> 2), r1l = r0l + 8;
    float t0 = 0.f, t1 = 0.f;
    #pragma unroll
    for (int g = 0; g < 8; g++) { t0 += rs[r0l * 8 + g]; t1 += rs[r1l * 8 + g]; }
    const float inv0 = 1.f / (t0 + 1e-6f);
    const float inv1 = 1.f / (t1 + 1e-6f);
    #pragma unroll
    for (int nt = 0; nt < 4; nt++) {
      const int col = wn + nt * 8 + (lane & 3) * 2;
      *(float2*)&ao[((size_t)(b * Nn + i0 + r0l)) * Cc + h * Dd + col] =
          make_float2(acc[nt][0] * inv0, acc[nt][1] * inv0);
      *(float2*)&ao[((size_t)(b * Nn + i0 + r1l)) * Cc + h * Dd + col] =
          make_float2(acc[nt][2] * inv1, acc[nt][3] * inv1);
    }
  }
}

// ---------------- launch ----------------
extern "C" void kernel_launch(void* const* d_in, const int* in_sizes, int n_in,
                              void* d_out, int out_size)
{
  const float* x     = (const float*)d_in[0];
  const float* Wqkv  = (const float*)d_in[1];
  const float* Wa    = (const float*)d_in[2];
  const float* ba    = (const float*)d_in[3];
  const float* Wproj = (const float*)d_in[4];
  const float* bproj = (const float*)d_in[5];
  float* out = (float*)d_out;

  float *qkv, *cbuf, *aobuf;
  cudaGetSymbolAddress((void**)&qkv,   g_qkv);
  cudaGetSymbolAddress((void**)&cbuf,  g_c);
  cudaGetSymbolAddress((void**)&aobuf, g_ao);

  cudaFuncSetAttribute(attn_kernel, cudaFuncAttributeMaxDynamicSharedMemorySize, ASMEM);
  cudaFuncSetAttribute(gemm_mma, cudaFuncAttributeMaxDynamicSharedMemorySize, GSMEM);

  // 1) qkv = x @ Wqkv^T (bf16 mma, 3-pass split)
  gemm_mma<<<dim3(3 * Cc / 128, Bb * Nn / 128), 256, GSMEM>>>(x, Wqkv, nullptr, qkv, Bb * Nn, 3 * Cc, Cc);
  // 2) gate logits
  gate_logits<<<Bb * Nn / 8, 256>>>(x, Wa, ba);
  // 3) prefix-sum of log gates per (b,h)
  gate_scan<<<Bb * Hh, 1024>>>();
  // 4) q/k silu+0.5 + L2 norm, in place
  qk_norm<<<Bb * Nn, 256>>>();
  // 5) attention (tensor cores, factorized decay mask)
  attn_kernel<<<dim3(Bb * Hh, Nn / 64), 256, ASMEM>>>(qkv, cbuf, aobuf);
  // 6) out = ao @ Wproj^T + bproj (bf16 mma, 3-pass split)
  gemm_mma<<<dim3(Cc / 128, Bb * Nn / 128), 256, GSMEM>>>(aobuf, Wproj, bproj, out, Bb * Nn, Cc, Cc);
}

// round 6
// speedup vs baseline: 2.4612x; 1.1121x over previous
#include <cuda_runtime.h>
#include <cuda_bf16.h>
#include <math.h>
#include <cstdint>

#define Bb 2
#define Nn 1024
#define Cc 768
#define Hh 12
#define Dd 64
#define ATT_SCALE 0.125f   // D^-0.5

// ---------------- scratch (static device memory; no allocations) ----------------
__device__ float g_qkv[Bb * Nn * 3 * Cc];      // [b, n, s, h, d] contiguous = [2048, 2304]
__device__ float g_z  [Bb * Nn * Hh];          // gate logits
__device__ float g_c  [Bb * Hh * (Nn + 1)];    // prefix sums of log a
__device__ float g_ao [Bb * Nn * Cc];          // attention output [b, n, h, d]

__device__ __forceinline__ uint32_t smem_u32(const void* p) {
  uint32_t a;
  asm("{ .reg .u64 t; cvta.to.shared.u64 t, %1; cvt.u32.u64 %0, t; }" : "=r"(a) : "l"(p));
  return a;
}

#define LDSM4(R0, R1, R2, R3, addr) \
  asm volatile("ldmatrix.sync.aligned.m8n8.x4.shared.b16 {%0,%1,%2,%3}, [%4];" \
               : "=r"(R0), "=r"(R1), "=r"(R2), "=r"(R3) : "r"(addr))

#define LDSM4T(R0, R1, R2, R3, addr) \
  asm volatile("ldmatrix.sync.aligned.m8n8.x4.trans.shared.b16 {%0,%1,%2,%3}, [%4];" \
               : "=r"(R0), "=r"(R1), "=r"(R2), "=r"(R3) : "r"(addr))

#define MMA16816(C, A0, A1, A2, A3, B0, B1) \
  asm volatile("mma.sync.aligned.m16n8k16.row.col.f32.bf16.bf16.f32 " \
               "{%0,%1,%2,%3}, {%4,%5,%6,%7}, {%8,%9}, {%0,%1,%2,%3};" \
               : "+f"((C)[0]), "+f"((C)[1]), "+f"((C)[2]), "+f"((C)[3]) \
               : "r"(A0), "r"(A1), "r"(A2), "r"(A3), "r"(B0), "r"(B1))

// split fp32x8 -> bf16 hi/lo x8 (2-term split; dropped lo*lo ~ 2^-16 relative)
__device__ __forceinline__ void cvt8(const float4 a, const float4 b, uint4& hi, uint4& lo) {
  __nv_bfloat162 h; float2 f; __nv_bfloat162 l;
  h = __floats2bfloat162_rn(a.x, a.y); hi.x = *(uint32_t*)&h; f = __bfloat1622float2(h);
  l = __floats2bfloat162_rn(a.x - f.x, a.y - f.y); lo.x = *(uint32_t*)&l;
  h = __floats2bfloat162_rn(a.z, a.w); hi.y = *(uint32_t*)&h; f = __bfloat1622float2(h);
  l = __floats2bfloat162_rn(a.z - f.x, a.w - f.y); lo.y = *(uint32_t*)&l;
  h = __floats2bfloat162_rn(b.x, b.y); hi.z = *(uint32_t*)&h; f = __bfloat1622float2(h);
  l = __floats2bfloat162_rn(b.x - f.x, b.y - f.y); lo.z = *(uint32_t*)&l;
  h = __floats2bfloat162_rn(b.z, b.w); hi.w = *(uint32_t*)&h; f = __bfloat1622float2(h);
  l = __floats2bfloat162_rn(b.z - f.x, b.w - f.y); lo.w = *(uint32_t*)&l;
}

// ============ tensor-core GEMM (bf16 3-pass split): C[M,N] = A[M,K] @ B[N,K]^T (+bias) ======
#define GPITCH 80
#define GMAT   (128 * GPITCH)       // 10240
#define GSTAGE (2 * GMAT)           // 20480
#define GSMEM  (2 * GSTAGE)         // 40960

__global__ __launch_bounds__(256, 1) void gemm_mma(
    const float* __restrict__ A, const float* __restrict__ B,
    const float* __restrict__ bias, float* __restrict__ Cout,
    int M, int N, int K)
{
  extern __shared__ char smc[];
  const uint32_t sb = smem_u32(smc);
  const int tid = threadIdx.x, wid = tid >> 5, lane = tid & 31;
  const int m0 = blockIdx.y * 128, n0 = blockIdx.x * 128;
  const int wm = (wid & 1) * 64, wn = (wid >> 1) * 32;

  const int lrow = tid >> 1;
  const int lcol = (tid & 1) * 8;
  const float* Ag = A + (size_t)(m0 + lrow) * K + lcol;
  const float* Bg = B + (size_t)(n0 + lrow) * K + lcol;
  const uint32_t stA = sb + lrow * GPITCH + (lcol ? 16 : 0);
  const uint32_t stB = stA + GMAT;

  const uint32_t aoff = (uint32_t)((wm + (lane & 15)) * GPITCH + ((lane >> 4) * 16));
  const uint32_t boff = (uint32_t)((wn + ((lane >> 4) << 3) + (lane & 7)) * GPITCH
                                   + (((lane >> 3) & 1) * 16)) + GMAT;

  float c[4][4][4] = {};
  const int NK = K / 16;

  float4 pa0, pa1, pb0, pb1;
  pa0 = *(const float4*)(Ag);     pa1 = *(const float4*)(Ag + 4);
  pb0 = *(const float4*)(Bg);     pb1 = *(const float4*)(Bg + 4);
  {
    uint4 hi, lo;
    cvt8(pa0, pa1, hi, lo);
    *(uint4*)(smc + (stA - sb))      = hi;
    *(uint4*)(smc + (stA - sb) + 32) = lo;
    cvt8(pb0, pb1, hi, lo);
    *(uint4*)(smc + (stB - sb))      = hi;
    *(uint4*)(smc + (stB - sb) + 32) = lo;
  }
  __syncthreads();

  for (int kc = 0; kc < NK; kc++) {
    const int s = kc & 1;
    if (kc + 1 < NK) {
      pa0 = *(const float4*)(Ag + (kc + 1) * 16);
      pa1 = *(const float4*)(Ag + (kc + 1) * 16 + 4);
      pb0 = *(const float4*)(Bg + (kc + 1) * 16);
      pb1 = *(const float4*)(Bg + (kc + 1) * 16 + 4);
    }

    const uint32_t stg = sb + s * GSTAGE;
    uint32_t ahi[4][4], alo[4][4], bhi[2][4], blo[2][4];
    #pragma unroll
    for (int mt = 0; mt < 4; mt++) {
      uint32_t ad = stg + aoff + mt * (16 * GPITCH);
      LDSM4(ahi[mt][0], ahi[mt][1], ahi[mt][2], ahi[mt][3], ad);
      LDSM4(alo[mt][0], alo[mt][1], alo[mt][2], alo[mt][3], ad + 32);
    }
    #pragma unroll
    for (int g = 0; g < 2; g++) {
      uint32_t bd = stg + boff + g * (16 * GPITCH);
      LDSM4(bhi[g][0], bhi[g][1], bhi[g][2], bhi[g][3], bd);
      LDSM4(blo[g][0], blo[g][1], blo[g][2], blo[g][3], bd + 32);
    }

    #pragma unroll
    for (int mt = 0; mt < 4; mt++) {
      #pragma unroll
      for (int nt = 0; nt < 4; nt++) {
        const int g = nt >> 1, q = (nt & 1) * 2;
        MMA16816(c[mt][nt], ahi[mt][0], ahi[mt][1], ahi[mt][2], ahi[mt][3], bhi[g][q], bhi[g][q + 1]);
        MMA16816(c[mt][nt], ahi[mt][0], ahi[mt][1], ahi[mt][2], ahi[mt][3], blo[g][q], blo[g][q + 1]);
        MMA16816(c[mt][nt], alo[mt][0], alo[mt][1], alo[mt][2], alo[mt][3], bhi[g][q], bhi[g][q + 1]);
      }
    }

    if (kc + 1 < NK) {
      const uint32_t dst = (stA - sb) + ((kc + 1) & 1) * GSTAGE;
      uint4 hi, lo;
      cvt8(pa0, pa1, hi, lo);
      *(uint4*)(smc + dst)      = hi;
      *(uint4*)(smc + dst + 32) = lo;
      cvt8(pb0, pb1, hi, lo);
      *(uint4*)(smc + dst + GMAT)      = hi;
      *(uint4*)(smc + dst + GMAT + 32) = lo;
    }
    __syncthreads();
  }

  #pragma unroll
  for (int mt = 0; mt < 4; mt++) {
    const int row = m0 + wm + mt * 16 + (lane >> 2);
    #pragma unroll
    for (int nt = 0; nt < 4; nt++) {
      const int col = n0 + wn + nt * 8 + (lane & 3) * 2;
      float bx = 0.f, by = 0.f;
      if (bias) { bx = __ldg(&bias[col]); by = __ldg(&bias[col + 1]); }
      *(float2*)&Cout[(size_t)row * N + col] =
          make_float2(c[mt][nt][0] + bx, c[mt][nt][1] + by);
      *(float2*)&Cout[(size_t)(row + 8) * N + col] =
          make_float2(c[mt][nt][2] + bx, c[mt][nt][3] + by);
    }
  }
}

// ---------------- gate logits ----------------
__global__ __launch_bounds__(256) void gate_logits(
    const float* __restrict__ x, const float* __restrict__ Wa, const float* __restrict__ ba)
{
  __shared__ float sW[Hh * Cc];   // 36 KB
  const int t = threadIdx.x;
  for (int i = t; i < Hh * Cc; i += 256) sW[i] = Wa[i];
  __syncthreads();

  const int warp = t >> 5, lane = t & 31;
  const int row = blockIdx.x * 8 + warp;
  const float* xr = x + (size_t)row * Cc;

  float acc[Hh] = {};
  for (int c0 = 0; c0 < Cc; c0 += 32) {
    float xv = xr[c0 + lane];
    #pragma unroll
    for (int h = 0; h < Hh; h++) acc[h] += xv * sW[h * Cc + c0 + lane];
  }
  #pragma unroll
  for (int h = 0; h < Hh; h++) {
    float v = acc[h];
    #pragma unroll
    for (int o = 16; o; o >>= 1) v += __shfl_xor_sync(0xffffffffu, v, o);
    if (lane == 0) g_z[(size_t)row * Hh + h] = v + ba[h];
  }
}

// ---------------- per-(b,h) scan ----------------
__global__ __launch_bounds__(1024) void gate_scan()
{
  __shared__ float sh[1024];
  const int bh = blockIdx.x;
  const int b = bh / Hh, h = bh % Hh;
  const int t = threadIdx.x;

  float la = 0.f;
  if (t > 0) {
    float z = g_z[((size_t)b * Nn + t) * Hh + h];
    float sp = (z > 15.f) ? z : log1pf(__expf(z));   // softplus
    la = -sp;
  }
  sh[t] = la;
  __syncthreads();
  #pragma unroll
  for (int off = 1; off < 1024; off <<= 1) {
    float v = (t >= off) ? sh[t - off] : 0.f;
    __syncthreads();
    sh[t] += v;
    __syncthreads();
  }
  float* cp = g_c + (size_t)bh * (Nn + 1);
  if (t == 0) cp[0] = 0.f;
  cp[t + 1] = sh[t];
}

// ---------------- q/k: silu(z)+0.5, L2-normalize ----------------
__global__ __launch_bounds__(256) void qk_norm()
{
  const int bn = blockIdx.x;
  const int warp = threadIdx.x >> 5, lane = threadIdx.x & 31;
  for (int task = warp; task < 2 * Hh; task += 8) {
    const int s = task & 1, h = task >> 1;
    float* p = g_qkv + (size_t)bn * 3 * Cc + s * Cc + h * Dd;
    float v0 = p[lane], v1 = p[lane + 32];
    float r0 = v0 / (1.f + __expf(-v0)) + 0.5f;
    float r1 = v1 / (1.f + __expf(-v1)) + 0.5f;
    float ss = r0 * r0 + r1 * r1;
    #pragma unroll
    for (int o = 16; o; o >>= 1) ss += __shfl_xor_sync(0xffffffffu, ss, o);
    float inv = rsqrtf(ss);
    p[lane] = r0 * inv;
    p[lane + 32] = r1 * inv;
  }
}

// ================= attention on tensor cores (bf16 3-pass) ======================
// i-block 64, stream 16 j-tiles of 64. SMEM matrices: 64 rows x pitch 144B.
//  Q [i][d] (A-layout), K [j][d] (B-layout), V [j][d] (B via ldmatrix.trans),
//  S [i][j] (A-layout for S.V). All split hi/lo.
#define APITCH 144
#define AMAT   (64 * APITCH)   // 9216
// byte offsets
#define O_QHI  0
#define O_QLO  (O_QHI + AMAT)
#define O_KHI  (O_QLO + AMAT)
#define O_KLO  (O_KHI + AMAT)
#define O_VHI  (O_KLO + AMAT)
#define O_VLO  (O_VHI + AMAT)
#define O_SHI  (O_VLO + AMAT)
#define O_SLO  (O_SHI + AMAT)
#define O_CI   (O_SLO + AMAT)          // 64 f
#define O_CI1  (O_CI  + 256)
#define O_CJ   (O_CI1 + 256)
#define O_CJ1  (O_CJ  + 256)
#define O_FI   (O_CJ1 + 256)
#define O_G    (O_FI  + 256)
#define O_H    (O_G   + 256)
#define O_RS   (O_H   + 256)           // 64 x 8 f
#define ASMEM  (O_RS + 64 * 8 * 4)     // 77568

__global__ __launch_bounds__(256, 2) void attn_kernel(
    const float* __restrict__ qkv, const float* __restrict__ cbuf, float* __restrict__ ao)
{
  extern __shared__ char smc[];
  const uint32_t sb = smem_u32(smc);
  float* ci  = (float*)(smc + O_CI);
  float* ci1 = (float*)(smc + O_CI1);
  float* cj  = (float*)(smc + O_CJ);
  float* cj1 = (float*)(smc + O_CJ1);
  float* sFi = (float*)(smc + O_FI);
  float* sG  = (float*)(smc + O_G);
  float* sH  = (float*)(smc + O_H);
  float* rs  = (float*)(smc + O_RS);

  const int bh = blockIdx.x;
  const int b = bh / Hh, h = bh % Hh;
  const int by = blockIdx.y;
  const int i0 = by * 64;
  const int tid = threadIdx.x, wid = tid >> 5, lane = tid & 31;
  const int wm = (wid & 3) * 16;        // S/out row group
  const int wn = (wid >> 2) * 32;       // S col group (phase A) / d col group (phase B)

  const float* cb = cbuf + (size_t)bh * (Nn + 1);
  const float* qbase = qkv + (size_t)b * Nn * 3 * Cc + h * Dd;
  const float* kbase = qbase + Cc;
  const float* vbase = qbase + 2 * Cc;

  // loader assignment: thread -> row (0..63), quarter q (16 floats)
  const int lrow = tid >> 2, lq = tid & 3;

  // stage Q (once): [i][d] hi/lo
  {
    const float* src = qbase + (size_t)(i0 + lrow) * 3 * Cc + lq * 16;
    float4 f0 = *(const float4*)(src);
    float4 f1 = *(const float4*)(src + 4);
    float4 f2 = *(const float4*)(src + 8);
    float4 f3 = *(const float4*)(src + 12);
    uint4 hi, lo;
    cvt8(f0, f1, hi, lo);
    *(uint4*)(smc + O_QHI + lrow * APITCH + lq * 32)      = hi;
    *(uint4*)(smc + O_QLO + lrow * APITCH + lq * 32)      = lo;
    cvt8(f2, f3, hi, lo);
    *(uint4*)(smc + O_QHI + lrow * APITCH + lq * 32 + 16) = hi;
    *(uint4*)(smc + O_QLO + lrow * APITCH + lq * 32 + 16) = lo;
  }
  if (tid < 64) {
    ci[tid]  = cb[i0 + tid];
    ci1[tid] = cb[i0 + tid + 1];
    sFi[tid] = __expf(cb[i0 + tid] - cb[i0]);   // <= 1
  }
  __syncthreads();

  // hoisted Q frags (A operand), 4 k-steps over d
  const uint32_t aoff = (uint32_t)((wm + (lane & 15)) * APITCH + ((lane >> 4) * 16));
  uint32_t qh[4][4], ql[4][4];
  #pragma unroll
  for (int k = 0; k < 4; k++) {
    uint32_t ad = sb + O_QHI + aoff + k * 32;
    LDSM4(qh[k][0], qh[k][1], qh[k][2], qh[k][3], ad);
    LDSM4(ql[k][0], ql[k][1], ql[k][2], ql[k][3], ad + AMAT);
  }

  // B-operand frag base (rows = n dim) for K (non-trans)
  const uint32_t boff = (uint32_t)((wn + ((lane >> 4) << 3) + (lane & 7)) * APITCH
                                   + (((lane >> 3) & 1) * 16));
  // V trans-ldmatrix base: rows = j (k dim), col-byte = wn*2 + (lane>>4)*16
  const uint32_t voff = (uint32_t)((lane & 15) * APITCH + wn * 2 + ((lane >> 4) * 16));

  float acc[4][4] = {};     // out frags [d-tile][4]
  float rsum0 = 0.f, rsum1 = 0.f;

  // prefetch tile 0 (K, V rows) into registers
  float4 pk[4], pv[4];
  {
    const float* sK = kbase + (size_t)lrow * 3 * Cc + lq * 16;
    const float* sV = vbase + (size_t)lrow * 3 * Cc + lq * 16;
    pk[0] = *(const float4*)(sK);     pk[1] = *(const float4*)(sK + 4);
    pk[2] = *(const float4*)(sK + 8); pk[3] = *(const float4*)(sK + 12);
    pv[0] = *(const float4*)(sV);     pv[1] = *(const float4*)(sV + 4);
    pv[2] = *(const float4*)(sV + 8); pv[3] = *(const float4*)(sV + 12);
  }

  for (int jt = 0; jt < 16; jt++) {
    const int j0 = jt * 64;
    __syncthreads();   // previous tile done with K/V/S

    // store staged K/V (from prefetch regs) as [j][d] hi/lo
    {
      uint4 hi, lo;
      cvt8(pk[0], pk[1], hi, lo);
      *(uint4*)(smc + O_KHI + lrow * APITCH + lq * 32)      = hi;
      *(uint4*)(smc + O_KLO + lrow * APITCH + lq * 32)      = lo;
      cvt8(pk[2], pk[3], hi, lo);
      *(uint4*)(smc + O_KHI + lrow * APITCH + lq * 32 + 16) = hi;
      *(uint4*)(smc + O_KLO + lrow * APITCH + lq * 32 + 16) = lo;
      cvt8(pv[0], pv[1], hi, lo);
      *(uint4*)(smc + O_VHI + lrow * APITCH + lq * 32)      = hi;
      *(uint4*)(smc + O_VLO + lrow * APITCH + lq * 32)      = lo;
      cvt8(pv[2], pv[3], hi, lo);
      *(uint4*)(smc + O_VHI + lrow * APITCH + lq * 32 + 16) = hi;
      *(uint4*)(smc + O_VLO + lrow * APITCH + lq * 32 + 16) = lo;
    }
    // per-tile mask factors
    if (jt == by) {
      if (tid < 64) { cj[tid] = cb[j0 + tid]; cj1[tid] = cb[j0 + tid + 1]; }
    } else if (jt < by) {
      if (tid < 64) sG[tid] = __expf(cb[i0] - cb[j0 + tid]);
    } else {
      if (tid < 64)        sG[tid]       = __expf(cb[j0 + tid + 1] - cb[j0]);
      else if (tid < 128)  sH[tid - 64]  = __expf(cb[j0] - cb[i0 + (tid - 64) + 1]);
    }
    __syncthreads();

    // prefetch next tile's K/V rows (latency hidden under phase A/B)
    if (jt + 1 < 16) {
      const float* sK = kbase + (size_t)(j0 + 64 + lrow) * 3 * Cc + lq * 16;
      const float* sV = vbase + (size_t)(j0 + 64 + lrow) * 3 * Cc + lq * 16;
      pk[0] = *(const float4*)(sK);     pk[1] = *(const float4*)(sK + 4);
      pk[2] = *(const float4*)(sK + 8); pk[3] = *(const float4*)(sK + 12);
      pv[0] = *(const float4*)(sV);     pv[1] = *(const float4*)(sV + 4);
      pv[2] = *(const float4*)(sV + 8); pv[3] = *(const float4*)(sV + 12);
    }

    // ---- phase A: S = Q.K^T (3-pass) ----
    float s[4][4] = {};
    #pragma unroll
    for (int k = 0; k < 4; k++) {
      uint32_t bd0 = sb + O_KHI + boff + k * 32;
      uint32_t bd1 = bd0 + 16 * APITCH;
      uint32_t kh0[4], kl0[4], kh1[4], kl1[4];
      LDSM4(kh0[0], kh0[1], kh0[2], kh0[3], bd0);
      LDSM4(kl0[0], kl0[1], kl0[2], kl0[3], bd0 + AMAT);
      LDSM4(kh1[0], kh1[1], kh1[2], kh1[3], bd1);
      LDSM4(kl1[0], kl1[1], kl1[2], kl1[3], bd1 + AMAT);
      #pragma unroll
      for (int nt = 0; nt < 4; nt++) {
        const uint32_t* KH = (nt < 2) ? kh0 : kh1;
        const uint32_t* KL = (nt < 2) ? kl0 : kl1;
        const int q = (nt & 1) * 2;
        MMA16816(s[nt], qh[k][0], qh[k][1], qh[k][2], qh[k][3], KH[q], KH[q + 1]);
        MMA16816(s[nt], qh[k][0], qh[k][1], qh[k][2], qh[k][3], KL[q], KL[q + 1]);
        MMA16816(s[nt], ql[k][0], ql[k][1], ql[k][2], ql[k][3], KH[q], KH[q + 1]);
      }
    }

    // ---- mask + rowsum + store S (bf16 hi/lo) ----
    const int r0l = wm + (lane >> 2);          // local i of frag rows 0/1
    const int r1l = r0l + 8;
    if (jt == by) {
      #pragma unroll
      for (int nt = 0; nt < 4; nt++) {
        const int jl = wn + nt * 8 + (lane & 3) * 2;
        #pragma unroll
        for (int e = 0; e < 4; e++) {
          const int il = (e < 2) ? r0l : r1l;
          const int jj = jl + (e & 1);
          const int ig = i0 + il, jg = j0 + jj;
          float arg = (jg < ig) ? (ci[il] - cj[jj]) : ((jg > ig) ? (cj1[jj] - ci1[il]) : 0.f);
          s[nt][e] = s[nt][e] * ATT_SCALE * __expf(arg);
        }
      }
    } else {
      const float* rf = (jt < by) ? sFi : sH;
      const float f0 = ATT_SCALE * rf[r0l];
      const float f1 = ATT_SCALE * rf[r1l];
      #pragma unroll
      for (int nt = 0; nt < 4; nt++) {
        const int jl = wn + nt * 8 + (lane & 3) * 2;
        const float g0 = sG[jl], g1 = sG[jl + 1];
        s[nt][0] *= f0 * g0; s[nt][1] *= f0 * g1;
        s[nt][2] *= f1 * g0; s[nt][3] *= f1 * g1;
      }
    }
    #pragma unroll
    for (int nt = 0; nt < 4; nt++) {
      rsum0 += s[nt][0] + s[nt][1];
      rsum1 += s[nt][2] + s[nt][3];
      const int jl = wn + nt * 8 + (lane & 3) * 2;
      __nv_bfloat162 h0 = __floats2bfloat162_rn(s[nt][0], s[nt][1]);
      float2 hf0 = __bfloat1622float2(h0);
      __nv_bfloat162 l0 = __floats2bfloat162_rn(s[nt][0] - hf0.x, s[nt][1] - hf0.y);
      __nv_bfloat162 h1 = __floats2bfloat162_rn(s[nt][2], s[nt][3]);
      float2 hf1 = __bfloat1622float2(h1);
      __nv_bfloat162 l1 = __floats2bfloat162_rn(s[nt][2] - hf1.x, s[nt][3] - hf1.y);
      *(uint32_t*)(smc + O_SHI + r0l * APITCH + jl * 2) = *(uint32_t*)&h0;
      *(uint32_t*)(smc + O_SLO + r0l * APITCH + jl * 2) = *(uint32_t*)&l0;
      *(uint32_t*)(smc + O_SHI + r1l * APITCH + jl * 2) = *(uint32_t*)&h1;
      *(uint32_t*)(smc + O_SLO + r1l * APITCH + jl * 2) = *(uint32_t*)&l1;
    }
    __syncthreads();

    // ---- phase B: acc += S.V (3-pass), k = j dim; V frags via ldmatrix.trans ----
    #pragma unroll
    for (int k = 0; k < 4; k++) {
      uint32_t ad = sb + O_SHI + aoff + k * 32;
      uint32_t sh4[4], sl4[4];
      LDSM4(sh4[0], sh4[1], sh4[2], sh4[3], ad);
      LDSM4(sl4[0], sl4[1], sl4[2], sl4[3], ad + AMAT);
      uint32_t vd0 = sb + O_VHI + voff + k * (16 * APITCH);
      uint32_t vd1 = vd0 + 32;   // +16 d columns
      uint32_t vh0[4], vl0[4], vh1[4], vl1[4];
      LDSM4T(vh0[0], vh0[1], vh0[2], vh0[3], vd0);
      LDSM4T(vl0[0], vl0[1], vl0[2], vl0[3], vd0 + AMAT);
      LDSM4T(vh1[0], vh1[1], vh1[2], vh1[3], vd1);
      LDSM4T(vl1[0], vl1[1], vl1[2], vl1[3], vd1 + AMAT);
      #pragma unroll
      for (int nt = 0; nt < 4; nt++) {
        const uint32_t* VH = (nt < 2) ? vh0 : vh1;
        const uint32_t* VL = (nt < 2) ? vl0 : vl1;
        const int q = (nt & 1) * 2;
        MMA16816(acc[nt], sh4[0], sh4[1], sh4[2], sh4[3], VH[q], VH[q + 1]);
        MMA16816(acc[nt], sh4[0], sh4[1], sh4[2], sh4[3], VL[q], VL[q + 1]);
        MMA16816(acc[nt], sl4[0], sl4[1], sl4[2], sl4[3], VH[q], VH[q + 1]);
      }
    }
  }

  // ---- rowsum reduce + normalize + write ----
  __syncthreads();
  {
    const int r0l = wm + (lane >> 2);
    const int slot = (wid >> 2) * 4 + (lane & 3);
    rs[r0l * 8 + slot]       = rsum0;
    rs[(r0l + 8) * 8 + slot] = rsum1;
  }
  __syncthreads();
  {
    const int r0l = wm + (lane >> 2), r1l = r0l + 8;
    float t0 = 0.f, t1 = 0.f;
    #pragma unroll
    for (int g = 0; g < 8; g++) { t0 += rs[r0l * 8 + g]; t1 += rs[r1l * 8 + g]; }
    const float inv0 = 1.f / (t0 + 1e-6f);
    const float inv1 = 1.f / (t1 + 1e-6f);
    #pragma unroll
    for (int nt = 0; nt < 4; nt++) {
      const int col = wn + nt * 8 + (lane & 3) * 2;
      *(float2*)&ao[((size_t)(b * Nn + i0 + r0l)) * Cc + h * Dd + col] =
          make_float2(acc[nt][0] * inv0, acc[nt][1] * inv0);
      *(float2*)&ao[((size_t)(b * Nn + i0 + r1l)) * Cc + h * Dd + col] =
          make_float2(acc[nt][2] * inv1, acc[nt][3] * inv1);
    }
  }
}

// ---------------- launch ----------------
extern "C" void kernel_launch(void* const* d_in, const int* in_sizes, int n_in,
                              void* d_out, int out_size)
{
  const float* x     = (const float*)d_in[0];
  const float* Wqkv  = (const float*)d_in[1];
  const float* Wa    = (const float*)d_in[2];
  const float* ba    = (const float*)d_in[3];
  const float* Wproj = (const float*)d_in[4];
  const float* bproj = (const float*)d_in[5];
  float* out = (float*)d_out;

  float *qkv, *cbuf, *aobuf;
  cudaGetSymbolAddress((void**)&qkv,   g_qkv);
  cudaGetSymbolAddress((void**)&cbuf,  g_c);
  cudaGetSymbolAddress((void**)&aobuf, g_ao);

  cudaFuncSetAttribute(attn_kernel, cudaFuncAttributeMaxDynamicSharedMemorySize, ASMEM);
  cudaFuncSetAttribute(gemm_mma, cudaFuncAttributeMaxDynamicSharedMemorySize, GSMEM);

  // 1) qkv = x @ Wqkv^T (bf16 mma, 3-pass split)
  gemm_mma<<<dim3(3 * Cc / 128, Bb * Nn / 128), 256, GSMEM>>>(x, Wqkv, nullptr, qkv, Bb * Nn, 3 * Cc, Cc);
  // 2) gate logits
  gate_logits<<<Bb * Nn / 8, 256>>>(x, Wa, ba);
  // 3) prefix-sum of log gates per (b,h)
  gate_scan<<<Bb * Hh, 1024>>>();
  // 4) q/k silu+0.5 + L2 norm, in place
  qk_norm<<<Bb * Nn, 256>>>();
  // 5) attention (tensor cores, ldmatrix.trans V, reg-prefetch pipeline)
  attn_kernel<<<dim3(Bb * Hh, Nn / 64), 256, ASMEM>>>(qkv, cbuf, aobuf);
  // 6) out = ao @ Wproj^T + bproj (bf16 mma, 3-pass split)
  gemm_mma<<<dim3(Cc / 128, Bb * Nn / 128), 256, GSMEM>>>(aobuf, Wproj, bproj, out, Bb * Nn, Cc, Cc);
}